// round 3
// baseline (speedup 1.0000x reference)
#include <cuda_runtime.h>

// ---------------------------------------------------------------------------
// GraphSageNet on GB300 (sm_103a) — round 2 (alignment fix)
// Pipeline: conv1(3->64,relu) -> conv2(64->128,relu)+fused avgpool -> fc(*mask)
//           -> sage1(relu) -> sage2 -> out
// conv2 uses packed fma.rn.f32x2 (FFMA2) for 2x fp32 FMA throughput.
// R2 fix: __shared__ float arrays only get 4B alignment; ws followed a
// 14280-byte xs so all float4 loads from ws were base+8 — misaligned address.
// ---------------------------------------------------------------------------

#define B_   32
#define N_   32
#define HID_ 256
#define OUT_ 128

// scratch (allocation-free contract: __device__ globals)
__device__ __align__(16) float g_conv1[1024 * 64 * 32 * 32];   // conv1 out (relu)
__device__ __align__(16) float g_pool [1024 * 128];            // pooled conv2 out
__device__ __align__(16) float g_h1   [1024 * 256];            // fc out * mask
__device__ __align__(16) float g_h2   [1024 * 256];            // sage1 out (relu)

__device__ __forceinline__ unsigned long long pack2(float lo, float hi) {
    unsigned long long d;
    asm("mov.b64 %0, {%1, %2};" : "=l"(d)
        : "r"(__float_as_uint(lo)), "r"(__float_as_uint(hi)));
    return d;
}
__device__ __forceinline__ void unpack2(unsigned long long v, float& lo, float& hi) {
    unsigned a, b;
    asm("mov.b64 {%0, %1}, %2;" : "=r"(a), "=r"(b) : "l"(v));
    lo = __uint_as_float(a); hi = __uint_as_float(b);
}
__device__ __forceinline__ void fma2(unsigned long long& d, unsigned long long a,
                                     unsigned long long b, unsigned long long c) {
    asm("fma.rn.f32x2 %0, %1, %2, %3;" : "=l"(d) : "l"(a), "l"(b), "l"(c));
}

// ---------------------------------------------------------------------------
// conv1: [1024,3,32,32] -> relu -> g_conv1 [1024,64,32,32]
// one block per image; thread tile = 8 oc x 8 px
// ---------------------------------------------------------------------------
__global__ void __launch_bounds__(256) conv1_kernel(const float* __restrict__ x,
                                                    const float* __restrict__ w,
                                                    const float* __restrict__ b) {
    __shared__ __align__(16) float ws[27 * 64];       // weights transposed: ws[k][oc]
    __shared__ __align__(16) float xs[3 * 34 * 35];   // padded input, row stride 35

    const int n = blockIdx.x, tid = threadIdx.x;

    for (int i = tid; i < 3 * 34 * 35; i += 256) xs[i] = 0.f;
    for (int i = tid; i < 64 * 27; i += 256) {
        int oc = i / 27, k = i % 27;
        ws[k * 64 + oc] = w[i];
    }
    __syncthreads();
    const float* xin = x + n * 3072;
    for (int i = tid; i < 3072; i += 256) {
        int ic = i >> 10, r = (i >> 5) & 31, c = i & 31;
        xs[ic * (34 * 35) + (r + 1) * 35 + (c + 1)] = xin[i];
    }
    __syncthreads();

    const int ocq = tid >> 5, oc0 = ocq * 8;
    float bias[8];
#pragma unroll
    for (int j = 0; j < 8; j++) bias[j] = b[oc0 + j];

    float* outp = g_conv1 + (size_t)n * 65536;

    for (int it = 0; it < 4; it++) {
        int pg = it * 32 + (tid & 31);
        int row = pg >> 2, colb = (pg & 3) * 8;
        float acc[8][8];
#pragma unroll
        for (int j = 0; j < 8; j++)
#pragma unroll
            for (int p = 0; p < 8; p++) acc[j][p] = bias[j];

#pragma unroll
        for (int ic = 0; ic < 3; ic++)
#pragma unroll
            for (int kr = 0; kr < 3; kr++) {
                int base = ic * (34 * 35) + (row + kr) * 35 + colb;
                float in10[10];
#pragma unroll
                for (int q = 0; q < 10; q++) in10[q] = xs[base + q];
#pragma unroll
                for (int kc = 0; kc < 3; kc++) {
                    int k = ic * 9 + kr * 3 + kc;
                    float4 w0 = *(const float4*)&ws[k * 64 + oc0];
                    float4 w1 = *(const float4*)&ws[k * 64 + oc0 + 4];
                    float wv[8] = {w0.x, w0.y, w0.z, w0.w, w1.x, w1.y, w1.z, w1.w};
#pragma unroll
                    for (int j = 0; j < 8; j++)
#pragma unroll
                        for (int p = 0; p < 8; p++)
                            acc[j][p] = fmaf(wv[j], in10[kc + p], acc[j][p]);
                }
            }
#pragma unroll
        for (int j = 0; j < 8; j++) {
            float4 v0 = make_float4(fmaxf(acc[j][0], 0.f), fmaxf(acc[j][1], 0.f),
                                    fmaxf(acc[j][2], 0.f), fmaxf(acc[j][3], 0.f));
            float4 v1 = make_float4(fmaxf(acc[j][4], 0.f), fmaxf(acc[j][5], 0.f),
                                    fmaxf(acc[j][6], 0.f), fmaxf(acc[j][7], 0.f));
            int o = (oc0 + j) * 1024 + row * 32 + colb;
            *(float4*)&outp[o]     = v0;
            *(float4*)&outp[o + 4] = v1;
        }
    }
}

// ---------------------------------------------------------------------------
// conv2 + relu + fused global avgpool.
// grid = (4 oc-groups, 1024 images); block 256.
// Thread tile: 4 oc x 8 px (4 packed f32x2 pixel pairs), fma.rn.f32x2.
// smem: weights [576][32] + input chunk [64][10][35]
// ---------------------------------------------------------------------------
#define C2_SMEM_BYTES ((576 * 32 + 64 * 10 * 35) * 4)

__global__ void __launch_bounds__(256) conv2_kernel(const float* __restrict__ w,
                                                    const float* __restrict__ bias) {
    extern __shared__ __align__(16) float sm[];
    float* w2s = sm;               // [k=576][ocl=32]
    float* xs  = sm + 576 * 32;    // [ic=64][rr=10][cc=35]

    const int ocg = blockIdx.x, n = blockIdx.y, tid = threadIdx.x;

    for (int i = tid; i < 32 * 576; i += 256) {
        int ocl = i / 576, k = i % 576;
        w2s[k * 32 + ocl] = w[(ocg * 32 + ocl) * 576 + k];
    }

    const int pxg = tid & 31, ocq = tid >> 5;
    const int row = pxg >> 2, colb = (pxg & 3) * 8;

    unsigned long long bp[4];
#pragma unroll
    for (int j = 0; j < 4; j++) {
        float bv = bias[ocg * 32 + ocq * 4 + j];
        bp[j] = pack2(bv, bv);
    }

    float psum[4] = {0.f, 0.f, 0.f, 0.f};
    const float* I = g_conv1 + (size_t)n * 65536;

    for (int chunk = 0; chunk < 4; chunk++) {
        __syncthreads();
        int r0 = chunk * 8;
        for (int i = tid; i < 64 * 10 * 35; i += 256) {
            int cc = i % 35, t2 = i / 35;
            int rr = t2 % 10, ic = t2 / 10;
            int c = cc - 1, r = r0 + rr - 1;
            float v = 0.f;
            if (c >= 0 && c < 32 && r >= 0 && r < 32) v = I[ic * 1024 + r * 32 + c];
            xs[i] = v;
        }
        __syncthreads();

        unsigned long long acc[4][4];
#pragma unroll
        for (int j = 0; j < 4; j++)
#pragma unroll
            for (int t = 0; t < 4; t++) acc[j][t] = bp[j];

        for (int ic = 0; ic < 64; ic++) {
#pragma unroll
            for (int kr = 0; kr < 3; kr++) {
                int base = ic * 350 + (row + kr) * 35 + colb;
                float in10[10];
#pragma unroll
                for (int q = 0; q < 10; q++) in10[q] = xs[base + q];
#pragma unroll
                for (int kc = 0; kc < 3; kc++) {
                    unsigned long long ip[4];
#pragma unroll
                    for (int t = 0; t < 4; t++)
                        ip[t] = pack2(in10[kc + 2 * t], in10[kc + 2 * t + 1]);
                    const float4 wv =
                        *(const float4*)&w2s[(ic * 9 + kr * 3 + kc) * 32 + ocq * 4];
                    unsigned long long wp[4];
                    wp[0] = pack2(wv.x, wv.x);
                    wp[1] = pack2(wv.y, wv.y);
                    wp[2] = pack2(wv.z, wv.z);
                    wp[3] = pack2(wv.w, wv.w);
#pragma unroll
                    for (int j = 0; j < 4; j++)
#pragma unroll
                        for (int t = 0; t < 4; t++)
                            fma2(acc[j][t], wp[j], ip[t], acc[j][t]);
                }
            }
        }
        // relu + pool for this row-chunk
#pragma unroll
        for (int j = 0; j < 4; j++) {
            float s = 0.f;
#pragma unroll
            for (int t = 0; t < 4; t++) {
                float lo, hi;
                unpack2(acc[j][t], lo, hi);
                s += fmaxf(lo, 0.f) + fmaxf(hi, 0.f);
            }
            psum[j] += s;
        }
    }

    // warp (= fixed ocq) covers all 1024 pixels -> warp reduce
#pragma unroll
    for (int off = 16; off; off >>= 1)
#pragma unroll
        for (int j = 0; j < 4; j++)
            psum[j] += __shfl_down_sync(0xffffffffu, psum[j], off);

    if ((tid & 31) == 0) {
#pragma unroll
        for (int j = 0; j < 4; j++)
            g_pool[n * 128 + ocg * 32 + ocq * 4 + j] = psum[j] * (1.f / 1024.f);
    }
}

// ---------------------------------------------------------------------------
// fc: g_pool [1024,128] @ fc_w.T + fc_b, * mask -> g_h1 [1024,256]
// block handles 8 rows; fc_w transposed into smem (conflict-free).
// ---------------------------------------------------------------------------
#define FC_SMEM_BYTES ((128 * 256 + 8 * 128) * 4)

__global__ void __launch_bounds__(256) fc_kernel(const float* __restrict__ fcw,
                                                 const float* __restrict__ fcb,
                                                 const float* __restrict__ mask) {
    extern __shared__ __align__(16) float sm[];
    float* ws = sm;               // [d=128][o=256]
    float* ps = sm + 128 * 256;   // [rr=8][d=128]
    const int row0 = blockIdx.x * 8, tid = threadIdx.x;

    for (int i = tid; i < 128 * 256; i += 256) {
        int o = i >> 7, d = i & 127;
        ws[d * 256 + o] = fcw[i];
    }
    for (int i = tid; i < 8 * 128; i += 256) ps[i] = g_pool[row0 * 128 + i];
    __syncthreads();

    const int o = tid;
    float acc[8];
    float bb = fcb[o];
#pragma unroll
    for (int rr = 0; rr < 8; rr++) acc[rr] = bb;
    for (int d = 0; d < 128; d++) {
        float wv = ws[d * 256 + o];
#pragma unroll
        for (int rr = 0; rr < 8; rr++) acc[rr] = fmaf(ps[rr * 128 + d], wv, acc[rr]);
    }
#pragma unroll
    for (int rr = 0; rr < 8; rr++) {
        int row = row0 + rr;
        g_h1[row * 256 + o] = acc[rr] * mask[row];
    }
}

// ---------------------------------------------------------------------------
// SAGE layer: out[b,n,o] = (relu)( sum_d agg*lw[o,d] + h*rw[o,d] + lb[o] )
// agg = (colsum - h)/31.  One block per batch b; agg/h interleaved in smem.
// FROM_H1 selects input; OUTD==256 writes g_h2, else writes `out`.
// ---------------------------------------------------------------------------
#define SAGE_SMEM_BYTES (32 * 256 * 2 * 4)

template <int OUTD, bool RELU, bool FROM_H1>
__global__ void __launch_bounds__(256) sage_kernel(const float* __restrict__ lw,
                                                   const float* __restrict__ lb,
                                                   const float* __restrict__ rw,
                                                   float* __restrict__ out) {
    extern __shared__ __align__(16) float sm[];   // [n=32][d=256][{agg,h}]
    const int b = blockIdx.x, tid = threadIdx.x;
    const float* hb = (FROM_H1 ? g_h1 : g_h2) + b * 32 * 256;

    for (int i = tid; i < 32 * 256; i += 256) {
        int nn = i >> 8, d = i & 255;
        sm[(nn * 256 + d) * 2 + 1] = hb[i];
    }
    __syncthreads();
    {
        const int d = tid;
        float s = 0.f;
#pragma unroll
        for (int nn = 0; nn < 32; nn++) s += sm[(nn * 256 + d) * 2 + 1];
#pragma unroll
        for (int nn = 0; nn < 32; nn++) {
            float hv = sm[(nn * 256 + d) * 2 + 1];
            sm[(nn * 256 + d) * 2] = (s - hv) * (1.f / 31.f);
        }
    }
    __syncthreads();

    const int o = tid;
    if (o < OUTD) {
        float acc[32];
        float bb = lb[o];
#pragma unroll
        for (int nn = 0; nn < 32; nn++) acc[nn] = bb;
        for (int d = 0; d < 256; d++) {
            float wl = lw[o * 256 + d];
            float wr = rw[o * 256 + d];
#pragma unroll
            for (int nn = 0; nn < 32; nn++) {
                float2 v = *(const float2*)&sm[(nn * 256 + d) * 2];
                acc[nn] += v.x * wl + v.y * wr;
            }
        }
#pragma unroll
        for (int nn = 0; nn < 32; nn++) {
            float r = acc[nn];
            if (RELU) r = fmaxf(r, 0.f);
            if (OUTD == 256)
                g_h2[(b * 32 + nn) * 256 + o] = r;
            else
                out[(b * 32 + nn) * OUTD + o] = r;
        }
    }
}

// ---------------------------------------------------------------------------
extern "C" void kernel_launch(void* const* d_in, const int* in_sizes, int n_in,
                              void* d_out, int out_size) {
    const float* x    = (const float*)d_in[0];
    const float* mask = (const float*)d_in[1];
    const float* c1w  = (const float*)d_in[2];
    const float* c1b  = (const float*)d_in[3];
    const float* c2w  = (const float*)d_in[4];
    const float* c2b  = (const float*)d_in[5];
    const float* fcw  = (const float*)d_in[6];
    const float* fcb  = (const float*)d_in[7];
    const float* s1lw = (const float*)d_in[8];
    const float* s1lb = (const float*)d_in[9];
    const float* s1rw = (const float*)d_in[10];
    const float* s2lw = (const float*)d_in[11];
    const float* s2lb = (const float*)d_in[12];
    const float* s2rw = (const float*)d_in[13];
    float* out = (float*)d_out;

    cudaFuncSetAttribute(conv2_kernel, cudaFuncAttributeMaxDynamicSharedMemorySize,
                         C2_SMEM_BYTES);
    cudaFuncSetAttribute(fc_kernel, cudaFuncAttributeMaxDynamicSharedMemorySize,
                         FC_SMEM_BYTES);
    cudaFuncSetAttribute(sage_kernel<256, true, true>,
                         cudaFuncAttributeMaxDynamicSharedMemorySize, SAGE_SMEM_BYTES);
    cudaFuncSetAttribute(sage_kernel<128, false, false>,
                         cudaFuncAttributeMaxDynamicSharedMemorySize, SAGE_SMEM_BYTES);

    conv1_kernel<<<1024, 256>>>(x, c1w, c1b);
    conv2_kernel<<<dim3(4, 1024), 256, C2_SMEM_BYTES>>>(c2w, c2b);
    fc_kernel<<<128, 256, FC_SMEM_BYTES>>>(fcw, fcb, mask);
    sage_kernel<256, true, true><<<32, 256, SAGE_SMEM_BYTES>>>(s1lw, s1lb, s1rw, out);
    sage_kernel<128, false, false><<<32, 256, SAGE_SMEM_BYTES>>>(s2lw, s2lb, s2rw, out);
}

// round 5
// speedup vs baseline: 2.1275x; 2.1275x over previous
#include <cuda_runtime.h>
#include <cuda_bf16.h>
#include <cstdint>

// ===========================================================================
// GraphSageNet GB300 (sm_103a harness, base sm_103 PTX target) — round 4.
// tcgen05 is unavailable (ptxas target is base sm_103). conv2 runs on the
// family-portable tensor path: ldmatrix + mma.sync.m16n8k16 bf16, 3-pass
// hi/lo compensation, fused bias+relu+avgpool epilogue in registers.
// ===========================================================================

#define NPAD 1280                      // padded px slots per image (34*34=1156)
#define GUARD 64
#define ROWS_TOTAL (GUARD + 1024 * NPAD + GUARD)

// scratch (allocation-free: __device__ globals, zero-initialized at load;
// pad/guard rows are never written so they stay zero across graph replays)
__device__ __align__(16) __nv_bfloat16 g_hi[(size_t)ROWS_TOTAL * 64];
__device__ __align__(16) __nv_bfloat16 g_lo[(size_t)ROWS_TOTAL * 64];
__device__ __align__(16) __nv_bfloat16 g_wh[2 * 9 * 4096];  // [ocg][s][64oc x 128B] SW128
__device__ __align__(16) __nv_bfloat16 g_wl[2 * 9 * 4096];
__device__ __align__(16) float g_pp[1024 * 128];            // pooled sums (x1024)
__device__ __align__(16) float g_h1[1024 * 256];
__device__ __align__(16) float g_h2[1024 * 256];

// ------------------------------- helpers -----------------------------------
__device__ __forceinline__ uint32_t smem_u32(const void* p) {
    uint32_t a;
    asm("{ .reg .u64 t; cvta.to.shared.u64 t, %1; cvt.u32.u64 %0, t; }"
        : "=r"(a) : "l"(p));
    return a;
}
__device__ __forceinline__ void ldsm4(uint32_t r[4], uint32_t addr) {
    asm volatile("ldmatrix.sync.aligned.m8n8.x4.shared.b16 {%0,%1,%2,%3}, [%4];"
                 : "=r"(r[0]), "=r"(r[1]), "=r"(r[2]), "=r"(r[3]) : "r"(addr));
}
__device__ __forceinline__ void mma16816(float* d, const uint32_t a[4],
                                         uint32_t b0, uint32_t b1) {
    asm volatile(
        "mma.sync.aligned.m16n8k16.row.col.f32.bf16.bf16.f32 "
        "{%0,%1,%2,%3}, {%4,%5,%6,%7}, {%8,%9}, {%0,%1,%2,%3};"
        : "+f"(d[0]), "+f"(d[1]), "+f"(d[2]), "+f"(d[3])
        : "r"(a[0]), "r"(a[1]), "r"(a[2]), "r"(a[3]), "r"(b0), "r"(b1));
}
#define CPA16(dst, src) \
    asm volatile("cp.async.cg.shared.global [%0], [%1], 16;" \
                 :: "r"(dst), "l"(src) : "memory")
#define CPA_WAIT() do {                                          \
    asm volatile("cp.async.commit_group;" ::: "memory");         \
    asm volatile("cp.async.wait_group 0;" ::: "memory");         \
} while (0)

// ---------------------------------------------------------------------------
// prep_w: conv2 weights -> bf16 hi/lo, SW128-swizzled tiles
// layout: [ocg 2][shift 9][64 oc rows x 128B]
// ---------------------------------------------------------------------------
__global__ void prep_w(const float* __restrict__ w) {
    int idx = blockIdx.x * 256 + threadIdx.x;
    if (idx >= 128 * 64 * 9) return;
    int s = idx % 9, t = idx / 9;
    int ic = t % 64, oc = t / 64;
    float v = w[oc * 576 + ic * 9 + s];
    __nv_bfloat16 h = __float2bfloat16_rn(v);
    __nv_bfloat16 l = __float2bfloat16_rn(v - __bfloat162float(h));
    int ocg = oc >> 6, ocl = oc & 63;
    uint32_t off = (uint32_t)(ocl * 128 + ic * 2);
    uint32_t sw = off ^ ((off >> 3) & 0x70);
    uint32_t base = ((uint32_t)ocg * 9 + (uint32_t)s) * 8192u;
    *(__nv_bfloat16*)((char*)g_wh + base + sw) = h;
    *(__nv_bfloat16*)((char*)g_wl + base + sw) = l;
}

// ---------------------------------------------------------------------------
// conv1: [1024,3,32,32] -> relu -> bf16 hi/lo, padded px-major [px][64 ic]
// ---------------------------------------------------------------------------
__global__ void __launch_bounds__(256) conv1_kernel(const float* __restrict__ x,
                                                    const float* __restrict__ w,
                                                    const float* __restrict__ b) {
    __shared__ __align__(16) float ws[27 * 64];
    __shared__ __align__(16) float xs[3 * 34 * 35];

    const int n = blockIdx.x, tid = threadIdx.x;

    for (int i = tid; i < 3 * 34 * 35; i += 256) xs[i] = 0.f;
    for (int i = tid; i < 64 * 27; i += 256) {
        int oc = i / 27, k = i % 27;
        ws[k * 64 + oc] = w[i];
    }
    __syncthreads();
    const float* xin = x + n * 3072;
    for (int i = tid; i < 3072; i += 256) {
        int ic = i >> 10, r = (i >> 5) & 31, c = i & 31;
        xs[ic * (34 * 35) + (r + 1) * 35 + (c + 1)] = xin[i];
    }
    __syncthreads();

    const int ocq = tid >> 5, oc0 = ocq * 8;
    float bias[8];
#pragma unroll
    for (int j = 0; j < 8; j++) bias[j] = b[oc0 + j];

    for (int it = 0; it < 4; it++) {
        int pg = it * 32 + (tid & 31);
        int row = pg >> 2, colb = (pg & 3) * 8;
        float acc[8][8];
#pragma unroll
        for (int j = 0; j < 8; j++)
#pragma unroll
            for (int p = 0; p < 8; p++) acc[j][p] = bias[j];

#pragma unroll
        for (int ic = 0; ic < 3; ic++)
#pragma unroll
            for (int kr = 0; kr < 3; kr++) {
                int base = ic * (34 * 35) + (row + kr) * 35 + colb;
                float in10[10];
#pragma unroll
                for (int q = 0; q < 10; q++) in10[q] = xs[base + q];
#pragma unroll
                for (int kc = 0; kc < 3; kc++) {
                    int k = ic * 9 + kr * 3 + kc;
                    float4 w0 = *(const float4*)&ws[k * 64 + oc0];
                    float4 w1 = *(const float4*)&ws[k * 64 + oc0 + 4];
                    float wv[8] = {w0.x, w0.y, w0.z, w0.w, w1.x, w1.y, w1.z, w1.w};
#pragma unroll
                    for (int j = 0; j < 8; j++)
#pragma unroll
                        for (int p = 0; p < 8; p++)
                            acc[j][p] = fmaf(wv[j], in10[kc + p], acc[j][p]);
                }
            }
#pragma unroll
        for (int p = 0; p < 8; p++) {
            int col = colb + p;
            size_t pxa = (size_t)GUARD + (size_t)n * NPAD + (row + 1) * 34 + (col + 1);
            uint32_t hq[4], lq[4];
#pragma unroll
            for (int pr = 0; pr < 4; pr++) {
                float v0 = fmaxf(acc[2 * pr][p], 0.f);
                float v1 = fmaxf(acc[2 * pr + 1][p], 0.f);
                __nv_bfloat16 h0 = __float2bfloat16_rn(v0);
                __nv_bfloat16 h1 = __float2bfloat16_rn(v1);
                __nv_bfloat16 l0 = __float2bfloat16_rn(v0 - __bfloat162float(h0));
                __nv_bfloat16 l1 = __float2bfloat16_rn(v1 - __bfloat162float(h1));
                hq[pr] = (uint32_t)__bfloat16_as_ushort(h0) |
                         ((uint32_t)__bfloat16_as_ushort(h1) << 16);
                lq[pr] = (uint32_t)__bfloat16_as_ushort(l0) |
                         ((uint32_t)__bfloat16_as_ushort(l1) << 16);
            }
            *(uint4*)&g_hi[pxa * 64 + oc0] = make_uint4(hq[0], hq[1], hq[2], hq[3]);
            *(uint4*)&g_lo[pxa * 64 + oc0] = make_uint4(lq[0], lq[1], lq[2], lq[3]);
        }
    }
}

// ---------------------------------------------------------------------------
// conv2 via mma.sync: grid (2 ocg, 1024 n), 256 threads (8 warps), 1 CTA/SM.
// warp tile 32px x 32oc; 10 px-tiles of 128; K = 9 shifts x 64 ic, 3 passes.
// smem: Wh 73728 | Wl 73728 | slabH 25344 | slabL 25344 | bias 256 | red 1024
// ---------------------------------------------------------------------------
#define SM_WH 0
#define SM_WL 73728
#define SM_SH 147456
#define SM_SL 172800
#define SM_BIAS 198144
#define SM_RED 198400
#define C2_SMEM 199424

__global__ void __launch_bounds__(256, 1) conv2_mma(const float* __restrict__ bias) {
    extern __shared__ __align__(1024) char smc[];
    const uint32_t smb = smem_u32(smc);
    const int tid = threadIdx.x, wid = tid >> 5, lane = tid & 31;
    const int ocg = blockIdx.x, n = blockIdx.y;
    const int pxw = wid & 3, ocw = wid >> 2;

    // ---- stage weights (already swizzled) + bias ----
    {
        const uint4* srcH = (const uint4*)((const char*)g_wh + (size_t)ocg * 73728);
        const uint4* srcL = (const uint4*)((const char*)g_wl + (size_t)ocg * 73728);
        for (int i = tid; i < 4608; i += 256) {
            CPA16(smb + SM_WH + i * 16, srcH + i);
            CPA16(smb + SM_WL + i * 16, srcL + i);
        }
        CPA_WAIT();
    }
    if (tid < 64) ((float*)(smc + SM_BIAS))[tid] = bias[ocg * 64 + tid];

    const int l15 = lane & 15;
    const uint32_t lk = (uint32_t)((lane >> 4) * 16);

    // B ldmatrix addresses: fixed rows per warp (oc rows), vary only by s,k
    const int rB0 = ocw * 32 + l15;        // ntile-pair 0 rows
    const int rB1 = rB0 + 16;              // ntile-pair 1 rows
    const uint32_t swB0 = (uint32_t)((rB0 & 7) << 4);
    const uint32_t swB1 = (uint32_t)((rB1 & 7) << 4);

    // per-thread bias for the 8 output columns this thread owns
    float b8[8];
#pragma unroll
    for (int nt = 0; nt < 4; nt++)
#pragma unroll
        for (int bb = 0; bb < 2; bb++)
            b8[nt * 2 + bb] = bias[ocg * 64 + ocw * 32 + nt * 8 + (lane & 3) * 2 + bb];

    float psum[8];
#pragma unroll
    for (int i = 0; i < 8; i++) psum[i] = 0.f;

    const size_t img_base = (size_t)GUARD + (size_t)n * NPAD;
    const uint4* gh = (const uint4*)g_hi;
    const uint4* gl = (const uint4*)g_lo;

    for (int t = 0; t < 10; t++) {
        __syncthreads();   // previous tile's compute done before slab overwrite
        // ---- stage input slab rows [t*128-35, t*128+163), swizzled ----
        {
            size_t gbase = (img_base + (size_t)t * 128 - 35) * 8;
            for (int i = tid; i < 1584; i += 256) {
                int r = i >> 3, j = i & 7;
                uint32_t col = (uint32_t)(j * 16) ^ (uint32_t)((r & 7) << 4);
                uint32_t d = (uint32_t)(r * 128) + col;
                CPA16(smb + SM_SH + d, gh + gbase + (size_t)r * 8 + j);
                CPA16(smb + SM_SL + d, gl + gbase + (size_t)r * 8 + j);
            }
            CPA_WAIT();
        }
        __syncthreads();

        float acc[2][4][4];
#pragma unroll
        for (int mt = 0; mt < 2; mt++)
#pragma unroll
            for (int nt = 0; nt < 4; nt++)
#pragma unroll
                for (int rg = 0; rg < 4; rg++) acc[mt][nt][rg] = 0.f;

        for (int s = 0; s < 9; s++) {
            const int doff = (s / 3 - 1) * 34 + (s % 3 - 1);
            const int rA0 = 35 + doff + pxw * 32 + l15;
            const int rA1 = rA0 + 16;
            const uint32_t swA0 = (uint32_t)((rA0 & 7) << 4);
            const uint32_t swA1 = (uint32_t)((rA1 & 7) << 4);
            const uint32_t wtile = (uint32_t)(s * 8192);
#pragma unroll
            for (int pass = 0; pass < 3; pass++) {
                const uint32_t aBase = smb + (pass < 2 ? SM_SH : SM_SL);
                const uint32_t bBase = smb + (pass == 1 ? SM_WL : SM_WH) + wtile;
#pragma unroll
                for (int k = 0; k < 4; k++) {
                    const uint32_t kb = (uint32_t)(k * 32) + lk;
                    uint32_t a0[4], a1[4], b0[4], b1[4];
                    ldsm4(a0, aBase + (uint32_t)(rA0 * 128) + (kb ^ swA0));
                    ldsm4(a1, aBase + (uint32_t)(rA1 * 128) + (kb ^ swA1));
                    ldsm4(b0, bBase + (uint32_t)(rB0 * 128) + (kb ^ swB0));
                    ldsm4(b1, bBase + (uint32_t)(rB1 * 128) + (kb ^ swB1));
                    mma16816(acc[0][0], a0, b0[0], b0[2]);
                    mma16816(acc[0][1], a0, b0[1], b0[3]);
                    mma16816(acc[0][2], a0, b1[0], b1[2]);
                    mma16816(acc[0][3], a0, b1[1], b1[3]);
                    mma16816(acc[1][0], a1, b0[0], b0[2]);
                    mma16816(acc[1][1], a1, b0[1], b0[3]);
                    mma16816(acc[1][2], a1, b1[0], b1[2]);
                    mma16816(acc[1][3], a1, b1[1], b1[3]);
                }
            }
        }

        // ---- epilogue: bias + relu + masked pool accumulate ----
        bool inter[2][2];
#pragma unroll
        for (int mt = 0; mt < 2; mt++)
#pragma unroll
            for (int hh = 0; hh < 2; hh++) {
                int pl = t * 128 + pxw * 32 + mt * 16 + (lane >> 2) + hh * 8;
                int rr = pl / 34, cc = pl - rr * 34;
                inter[mt][hh] =
                    (pl < 1156) & (rr >= 1) & (rr <= 32) & (cc >= 1) & (cc <= 32);
            }
#pragma unroll
        for (int mt = 0; mt < 2; mt++)
#pragma unroll
            for (int nt = 0; nt < 4; nt++)
#pragma unroll
                for (int rg = 0; rg < 4; rg++) {
                    float v = fmaxf(acc[mt][nt][rg] + b8[nt * 2 + (rg & 1)], 0.f);
                    if (inter[mt][rg >> 1]) psum[nt * 2 + (rg & 1)] += v;
                }
    }

    // ---- reduce: xor over lane bits 2..4 sums px-rows within warp ----
#pragma unroll
    for (int off = 4; off <= 16; off <<= 1)
#pragma unroll
        for (int i = 0; i < 8; i++)
            psum[i] += __shfl_xor_sync(0xffffffffu, psum[i], off);

    float* red = (float*)(smc + SM_RED);   // [8 warps][32 cols]
    if (lane < 4) {
#pragma unroll
        for (int nt = 0; nt < 4; nt++)
#pragma unroll
            for (int bb = 0; bb < 2; bb++)
                red[wid * 32 + nt * 8 + lane * 2 + bb] = psum[nt * 2 + bb];
    }
    __syncthreads();
    if (tid < 64) {
        int oc2 = tid >> 5, c = tid & 31;
        float s = 0.f;
#pragma unroll
        for (int p = 0; p < 4; p++) s += red[(oc2 * 4 + p) * 32 + c];
        g_pp[n * 128 + ocg * 64 + oc2 * 32 + c] = s;
    }
}

// ---------------------------------------------------------------------------
// fc: (g_pp/1024) [1024,128] @ fc_w.T + fc_b, * mask -> g_h1 [1024,256]
// ---------------------------------------------------------------------------
#define FC_SMEM_BYTES ((128 * 256 + 8 * 128) * 4)

__global__ void __launch_bounds__(256) fc_kernel(const float* __restrict__ fcw,
                                                 const float* __restrict__ fcb,
                                                 const float* __restrict__ mask) {
    extern __shared__ __align__(16) float smf[];
    float* ws = smf;
    float* ps = smf + 128 * 256;
    const int row0 = blockIdx.x * 8, tid = threadIdx.x;

    for (int i = tid; i < 128 * 256; i += 256) {
        int o = i >> 7, d = i & 127;
        ws[d * 256 + o] = fcw[i];
    }
    for (int i = tid; i < 8 * 128; i += 256)
        ps[i] = g_pp[row0 * 128 + i] * (1.f / 1024.f);
    __syncthreads();

    const int o = tid;
    float acc[8];
    float bb = fcb[o];
#pragma unroll
    for (int rr = 0; rr < 8; rr++) acc[rr] = bb;
    for (int d = 0; d < 128; d++) {
        float wv = ws[d * 256 + o];
#pragma unroll
        for (int rr = 0; rr < 8; rr++) acc[rr] = fmaf(ps[rr * 128 + d], wv, acc[rr]);
    }
#pragma unroll
    for (int rr = 0; rr < 8; rr++) {
        int row = row0 + rr;
        g_h1[row * 256 + o] = acc[rr] * mask[row];
    }
}

// ---------------------------------------------------------------------------
// SAGE layer: grid (32 b, 4 node-segments of 8)
// ---------------------------------------------------------------------------
#define SAGE_SMEM_BYTES (32 * 256 * 2 * 4)

template <int OUTD, bool RELU, bool FROM_H1>
__global__ void __launch_bounds__(256) sage_kernel(const float* __restrict__ lw,
                                                   const float* __restrict__ lb,
                                                   const float* __restrict__ rw,
                                                   float* __restrict__ out) {
    extern __shared__ __align__(16) float sms[];  // [n=32][d=256][{agg,h}]
    const int b = blockIdx.x, tid = threadIdx.x;
    const int n0 = blockIdx.y * 8;
    const float* hb = (FROM_H1 ? g_h1 : g_h2) + b * 32 * 256;

    for (int i = tid; i < 32 * 256; i += 256) {
        int nn = i >> 8, d = i & 255;
        sms[(nn * 256 + d) * 2 + 1] = hb[i];
    }
    __syncthreads();
    {
        const int d = tid;
        float s = 0.f;
#pragma unroll
        for (int nn = 0; nn < 32; nn++) s += sms[(nn * 256 + d) * 2 + 1];
#pragma unroll
        for (int nn = 0; nn < 32; nn++) {
            float hv = sms[(nn * 256 + d) * 2 + 1];
            sms[(nn * 256 + d) * 2] = (s - hv) * (1.f / 31.f);
        }
    }
    __syncthreads();

    const int o = tid;
    if (o < OUTD) {
        float acc[8];
        float bb = lb[o];
#pragma unroll
        for (int nn = 0; nn < 8; nn++) acc[nn] = bb;
        for (int d = 0; d < 256; d++) {
            float wl = lw[o * 256 + d];
            float wr = rw[o * 256 + d];
#pragma unroll
            for (int nn = 0; nn < 8; nn++) {
                float2 v = *(const float2*)&sms[((n0 + nn) * 256 + d) * 2];
                acc[nn] += v.x * wl + v.y * wr;
            }
        }
#pragma unroll
        for (int nn = 0; nn < 8; nn++) {
            float r = acc[nn];
            if (RELU) r = fmaxf(r, 0.f);
            if (OUTD == 256)
                g_h2[(b * 32 + n0 + nn) * 256 + o] = r;
            else
                out[(b * 32 + n0 + nn) * OUTD + o] = r;
        }
    }
}

// ---------------------------------------------------------------------------
extern "C" void kernel_launch(void* const* d_in, const int* in_sizes, int n_in,
                              void* d_out, int out_size) {
    const float* x    = (const float*)d_in[0];
    const float* mask = (const float*)d_in[1];
    const float* c1w  = (const float*)d_in[2];
    const float* c1b  = (const float*)d_in[3];
    const float* c2w  = (const float*)d_in[4];
    const float* c2b  = (const float*)d_in[5];
    const float* fcw  = (const float*)d_in[6];
    const float* fcb  = (const float*)d_in[7];
    const float* s1lw = (const float*)d_in[8];
    const float* s1lb = (const float*)d_in[9];
    const float* s1rw = (const float*)d_in[10];
    const float* s2lw = (const float*)d_in[11];
    const float* s2lb = (const float*)d_in[12];
    const float* s2rw = (const float*)d_in[13];
    float* out = (float*)d_out;

    cudaFuncSetAttribute(conv2_mma, cudaFuncAttributeMaxDynamicSharedMemorySize,
                         C2_SMEM);
    cudaFuncSetAttribute(fc_kernel, cudaFuncAttributeMaxDynamicSharedMemorySize,
                         FC_SMEM_BYTES);
    cudaFuncSetAttribute(sage_kernel<256, true, true>,
                         cudaFuncAttributeMaxDynamicSharedMemorySize, SAGE_SMEM_BYTES);
    cudaFuncSetAttribute(sage_kernel<128, false, false>,
                         cudaFuncAttributeMaxDynamicSharedMemorySize, SAGE_SMEM_BYTES);

    prep_w<<<288, 256>>>(c2w);
    conv1_kernel<<<1024, 256>>>(x, c1w, c1b);
    conv2_mma<<<dim3(2, 1024), 256, C2_SMEM>>>(c2b);
    fc_kernel<<<128, 256, FC_SMEM_BYTES>>>(fcw, fcb, mask);
    sage_kernel<256, true, true>
        <<<dim3(32, 4), 256, SAGE_SMEM_BYTES>>>(s1lw, s1lb, s1rw, out);
    sage_kernel<128, false, false>
        <<<dim3(32, 4), 256, SAGE_SMEM_BYTES>>>(s2lw, s2lb, s2rw, out);
}

// round 6
// speedup vs baseline: 4.9678x; 2.3350x over previous
#include <cuda_runtime.h>
#include <cuda_fp16.h>
#include <cstdint>

// ===========================================================================
// GraphSageNet GB300 (sm_103a harness, base sm_103 ptx target) — round 5.
// conv2: ldmatrix + mma.sync m16n8k16 fp16, 2-pass weight hi/lo split
//        (a@wh + a@wl), 9 live px-tiles, double-buffered cp.async slabs,
//        fused bias+relu+avgpool epilogue.
// Split-B (weights) chosen so the residual activation rounding error is
// i.i.d. per pixel and averages out 32x in the 1024-px pool.
// ===========================================================================

#define NPAD 1280                      // padded px slots per image (34*34=1156)
#define GUARD 64
#define ROWS_TOTAL (GUARD + 1024 * NPAD + GUARD)

// scratch (__device__ globals, zero-init at load; pads never written)
__device__ __align__(16) __half g_act[(size_t)ROWS_TOTAL * 64];
__device__ __align__(16) __half g_wh[2 * 9 * 4096];  // [ocg][s][64oc x 128B] SW128
__device__ __align__(16) __half g_wl[2 * 9 * 4096];
__device__ __align__(16) float g_pp[1024 * 128];
__device__ __align__(16) float g_h1[1024 * 256];
__device__ __align__(16) float g_h2[1024 * 256];

// ------------------------------- helpers -----------------------------------
__device__ __forceinline__ uint32_t smem_u32(const void* p) {
    uint32_t a;
    asm("{ .reg .u64 t; cvta.to.shared.u64 t, %1; cvt.u32.u64 %0, t; }"
        : "=r"(a) : "l"(p));
    return a;
}
__device__ __forceinline__ void ldsm4(uint32_t r[4], uint32_t addr) {
    asm volatile("ldmatrix.sync.aligned.m8n8.x4.shared.b16 {%0,%1,%2,%3}, [%4];"
                 : "=r"(r[0]), "=r"(r[1]), "=r"(r[2]), "=r"(r[3]) : "r"(addr));
}
__device__ __forceinline__ void mma16816(float* d, const uint32_t a[4],
                                         uint32_t b0, uint32_t b1) {
    asm volatile(
        "mma.sync.aligned.m16n8k16.row.col.f32.f16.f16.f32 "
        "{%0,%1,%2,%3}, {%4,%5,%6,%7}, {%8,%9}, {%0,%1,%2,%3};"
        : "+f"(d[0]), "+f"(d[1]), "+f"(d[2]), "+f"(d[3])
        : "r"(a[0]), "r"(a[1]), "r"(a[2]), "r"(a[3]), "r"(b0), "r"(b1));
}
#define CPA16(dst, src) \
    asm volatile("cp.async.cg.shared.global [%0], [%1], 16;" \
                 :: "r"(dst), "l"(src) : "memory")
#define CPA_COMMIT() asm volatile("cp.async.commit_group;" ::: "memory")

// ---------------------------------------------------------------------------
// prep_w: conv2 weights -> fp16 hi/lo, SW128-swizzled [ocg 2][s 9][64 x 128B]
// ---------------------------------------------------------------------------
__global__ void prep_w(const float* __restrict__ w) {
    int idx = blockIdx.x * 256 + threadIdx.x;
    if (idx >= 128 * 64 * 9) return;
    int s = idx % 9, t = idx / 9;
    int ic = t % 64, oc = t / 64;
    float v = w[oc * 576 + ic * 9 + s];
    __half h = __float2half_rn(v);
    __half l = __float2half_rn(v - __half2float(h));
    int ocg = oc >> 6, ocl = oc & 63;
    uint32_t off = (uint32_t)(ocl * 128 + ic * 2);
    uint32_t sw = off ^ ((off >> 3) & 0x70);
    uint32_t base = ((uint32_t)ocg * 9 + (uint32_t)s) * 8192u;
    *(__half*)((char*)g_wh + base + sw) = h;
    *(__half*)((char*)g_wl + base + sw) = l;
}

// ---------------------------------------------------------------------------
// conv1: [1024,3,32,32] -> relu -> fp16, padded px-major [px][64 ic]
// ---------------------------------------------------------------------------
__global__ void __launch_bounds__(256) conv1_kernel(const float* __restrict__ x,
                                                    const float* __restrict__ w,
                                                    const float* __restrict__ b) {
    __shared__ __align__(16) float ws[27 * 64];
    __shared__ __align__(16) float xs[3 * 34 * 35];

    const int n = blockIdx.x, tid = threadIdx.x;

    for (int i = tid; i < 3 * 34 * 35; i += 256) xs[i] = 0.f;
    for (int i = tid; i < 64 * 27; i += 256) {
        int oc = i / 27, k = i % 27;
        ws[k * 64 + oc] = w[i];
    }
    __syncthreads();
    const float* xin = x + n * 3072;
    for (int i = tid; i < 3072; i += 256) {
        int ic = i >> 10, r = (i >> 5) & 31, c = i & 31;
        xs[ic * (34 * 35) + (r + 1) * 35 + (c + 1)] = xin[i];
    }
    __syncthreads();

    const int ocq = tid >> 5, oc0 = ocq * 8;
    float bias[8];
#pragma unroll
    for (int j = 0; j < 8; j++) bias[j] = b[oc0 + j];

    for (int it = 0; it < 4; it++) {
        int pg = it * 32 + (tid & 31);
        int row = pg >> 2, colb = (pg & 3) * 8;
        float acc[8][8];
#pragma unroll
        for (int j = 0; j < 8; j++)
#pragma unroll
            for (int p = 0; p < 8; p++) acc[j][p] = bias[j];

#pragma unroll
        for (int ic = 0; ic < 3; ic++)
#pragma unroll
            for (int kr = 0; kr < 3; kr++) {
                int base = ic * (34 * 35) + (row + kr) * 35 + colb;
                float in10[10];
#pragma unroll
                for (int q = 0; q < 10; q++) in10[q] = xs[base + q];
#pragma unroll
                for (int kc = 0; kc < 3; kc++) {
                    int k = ic * 9 + kr * 3 + kc;
                    float4 w0 = *(const float4*)&ws[k * 64 + oc0];
                    float4 w1 = *(const float4*)&ws[k * 64 + oc0 + 4];
                    float wv[8] = {w0.x, w0.y, w0.z, w0.w, w1.x, w1.y, w1.z, w1.w};
#pragma unroll
                    for (int j = 0; j < 8; j++)
#pragma unroll
                        for (int p = 0; p < 8; p++)
                            acc[j][p] = fmaf(wv[j], in10[kc + p], acc[j][p]);
                }
            }
#pragma unroll
        for (int p = 0; p < 8; p++) {
            int col = colb + p;
            size_t pxa = (size_t)GUARD + (size_t)n * NPAD + (row + 1) * 34 + (col + 1);
            uint32_t q[4];
#pragma unroll
            for (int pr = 0; pr < 4; pr++) {
                __half h0 = __float2half_rn(fmaxf(acc[2 * pr][p], 0.f));
                __half h1 = __float2half_rn(fmaxf(acc[2 * pr + 1][p], 0.f));
                q[pr] = (uint32_t)__half_as_ushort(h0) |
                        ((uint32_t)__half_as_ushort(h1) << 16);
            }
            *(uint4*)&g_act[pxa * 64 + oc0] = make_uint4(q[0], q[1], q[2], q[3]);
        }
    }
}

// ---------------------------------------------------------------------------
// conv2 via mma.sync: grid (2 ocg, 1024 n), 8 warps, 1 CTA/SM.
// warp tile 32px x 32oc; 9 px-tiles of 128; per k-step: a @ wh + a @ wl.
// smem: Wh 73728 | Wl 73728 | slab x2 bufs 25344 | bias | red
// ---------------------------------------------------------------------------
#define SM_WH 0
#define SM_WL 73728
#define SM_SLAB 147456
#define SLAB_BYTES 25344
#define SM_BIAS 198144
#define SM_RED 198400
#define C2_SMEM 199424

__global__ void __launch_bounds__(256, 1) conv2_mma(const float* __restrict__ bias) {
    extern __shared__ __align__(1024) char smc[];
    const uint32_t smb = smem_u32(smc);
    const int tid = threadIdx.x, wid = tid >> 5, lane = tid & 31;
    const int ocg = blockIdx.x, n = blockIdx.y;
    const int pxw = wid & 3, ocw = wid >> 2;

    const size_t img_base = (size_t)GUARD + (size_t)n * NPAD;
    const uint4* ga = (const uint4*)g_act;

    // ---- stage weights (pre-swizzled) + slab 0, one cp.async group ----
    {
        const uint4* srcH = (const uint4*)((const char*)g_wh + (size_t)ocg * 73728);
        const uint4* srcL = (const uint4*)((const char*)g_wl + (size_t)ocg * 73728);
        for (int i = tid; i < 4608; i += 256) {
            CPA16(smb + SM_WH + i * 16, srcH + i);
            CPA16(smb + SM_WL + i * 16, srcL + i);
        }
        size_t gbase = (img_base - 35) * 8;
        for (int i = tid; i < 1584; i += 256) {
            int r = i >> 3, j = i & 7;
            uint32_t d = (uint32_t)(r * 128) +
                         (((uint32_t)(j * 16)) ^ ((uint32_t)((r & 7) << 4)));
            CPA16(smb + SM_SLAB + d, ga + gbase + (size_t)r * 8 + j);
        }
        CPA_COMMIT();
    }
    if (tid < 64) ((float*)(smc + SM_BIAS))[tid] = bias[ocg * 64 + tid];

    const int l15 = lane & 15;
    const uint32_t lk = (uint32_t)((lane >> 4) * 16);
    const int rB0 = ocw * 32 + l15, rB1 = rB0 + 16;
    const uint32_t swB0 = (uint32_t)((rB0 & 7) << 4);
    const uint32_t swB1 = (uint32_t)((rB1 & 7) << 4);

    float b8[8];
#pragma unroll
    for (int nt = 0; nt < 4; nt++)
#pragma unroll
        for (int bb = 0; bb < 2; bb++)
            b8[nt * 2 + bb] = bias[ocg * 64 + ocw * 32 + nt * 8 + (lane & 3) * 2 + bb];

    float psum[8];
#pragma unroll
    for (int i = 0; i < 8; i++) psum[i] = 0.f;

    asm volatile("cp.async.wait_group 0;" ::: "memory");
    __syncthreads();

    for (int t = 0; t < 9; t++) {
        // issue next slab into the other buffer (prev compute there is done)
        if (t < 8) {
            size_t gbase = (img_base + (size_t)(t + 1) * 128 - 35) * 8;
            uint32_t sbase = smb + SM_SLAB + (uint32_t)(((t + 1) & 1) * SLAB_BYTES);
            for (int i = tid; i < 1584; i += 256) {
                int r = i >> 3, j = i & 7;
                uint32_t d = (uint32_t)(r * 128) +
                             (((uint32_t)(j * 16)) ^ ((uint32_t)((r & 7) << 4)));
                CPA16(sbase + d, ga + gbase + (size_t)r * 8 + j);
            }
            CPA_COMMIT();
            asm volatile("cp.async.wait_group 1;" ::: "memory");
        } else {
            asm volatile("cp.async.wait_group 0;" ::: "memory");
        }
        __syncthreads();

        const uint32_t sbA = smb + SM_SLAB + (uint32_t)((t & 1) * SLAB_BYTES);
        float acc[2][4][4];
#pragma unroll
        for (int mt = 0; mt < 2; mt++)
#pragma unroll
            for (int nt = 0; nt < 4; nt++)
#pragma unroll
                for (int rg = 0; rg < 4; rg++) acc[mt][nt][rg] = 0.f;

        for (int s = 0; s < 9; s++) {
            const int doff = (s / 3 - 1) * 34 + (s % 3 - 1);
            const int rA0 = 35 + doff + pxw * 32 + l15;
            const int rA1 = rA0 + 16;
            const uint32_t swA0 = (uint32_t)((rA0 & 7) << 4);
            const uint32_t swA1 = (uint32_t)((rA1 & 7) << 4);
            const uint32_t wt = (uint32_t)(s * 8192);
#pragma unroll
            for (int k = 0; k < 4; k++) {
                const uint32_t kb = (uint32_t)(k * 32) + lk;
                uint32_t a0[4], a1[4], bh0[4], bh1[4], bl0[4], bl1[4];
                ldsm4(a0, sbA + (uint32_t)(rA0 * 128) + (kb ^ swA0));
                ldsm4(a1, sbA + (uint32_t)(rA1 * 128) + (kb ^ swA1));
                ldsm4(bh0, smb + SM_WH + wt + (uint32_t)(rB0 * 128) + (kb ^ swB0));
                ldsm4(bh1, smb + SM_WH + wt + (uint32_t)(rB1 * 128) + (kb ^ swB1));
                ldsm4(bl0, smb + SM_WL + wt + (uint32_t)(rB0 * 128) + (kb ^ swB0));
                ldsm4(bl1, smb + SM_WL + wt + (uint32_t)(rB1 * 128) + (kb ^ swB1));
                mma16816(acc[0][0], a0, bh0[0], bh0[2]);
                mma16816(acc[0][1], a0, bh0[1], bh0[3]);
                mma16816(acc[0][2], a0, bh1[0], bh1[2]);
                mma16816(acc[0][3], a0, bh1[1], bh1[3]);
                mma16816(acc[1][0], a1, bh0[0], bh0[2]);
                mma16816(acc[1][1], a1, bh0[1], bh0[3]);
                mma16816(acc[1][2], a1, bh1[0], bh1[2]);
                mma16816(acc[1][3], a1, bh1[1], bh1[3]);
                mma16816(acc[0][0], a0, bl0[0], bl0[2]);
                mma16816(acc[0][1], a0, bl0[1], bl0[3]);
                mma16816(acc[0][2], a0, bl1[0], bl1[2]);
                mma16816(acc[0][3], a0, bl1[1], bl1[3]);
                mma16816(acc[1][0], a1, bl0[0], bl0[2]);
                mma16816(acc[1][1], a1, bl0[1], bl0[3]);
                mma16816(acc[1][2], a1, bl1[0], bl1[2]);
                mma16816(acc[1][3], a1, bl1[1], bl1[3]);
            }
        }

        // ---- epilogue: bias + relu + masked pool accumulate ----
        bool inter[2][2];
#pragma unroll
        for (int mt = 0; mt < 2; mt++)
#pragma unroll
            for (int hh = 0; hh < 2; hh++) {
                int pl = t * 128 + pxw * 32 + mt * 16 + (lane >> 2) + hh * 8;
                int rr = pl / 34, cc = pl - rr * 34;
                inter[mt][hh] =
                    (pl < 1156) & (rr >= 1) & (rr <= 32) & (cc >= 1) & (cc <= 32);
            }
#pragma unroll
        for (int mt = 0; mt < 2; mt++)
#pragma unroll
            for (int nt = 0; nt < 4; nt++)
#pragma unroll
                for (int rg = 0; rg < 4; rg++) {
                    float v = fmaxf(acc[mt][nt][rg] + b8[nt * 2 + (rg & 1)], 0.f);
                    if (inter[mt][rg >> 1]) psum[nt * 2 + (rg & 1)] += v;
                }
        __syncthreads();  // compute done before next-next slab overwrites buffer
    }

    // ---- reduce: xor over lane bits 2..4 sums px-rows within warp ----
#pragma unroll
    for (int off = 4; off <= 16; off <<= 1)
#pragma unroll
        for (int i = 0; i < 8; i++)
            psum[i] += __shfl_xor_sync(0xffffffffu, psum[i], off);

    float* red = (float*)(smc + SM_RED);   // [8 warps][32 cols]
    if (lane < 4) {
#pragma unroll
        for (int nt = 0; nt < 4; nt++)
#pragma unroll
            for (int bb = 0; bb < 2; bb++)
                red[wid * 32 + nt * 8 + lane * 2 + bb] = psum[nt * 2 + bb];
    }
    __syncthreads();
    if (tid < 64) {
        int oc2 = tid >> 5, c = tid & 31;
        float s = 0.f;
#pragma unroll
        for (int p = 0; p < 4; p++) s += red[(oc2 * 4 + p) * 32 + c];
        g_pp[n * 128 + ocg * 64 + oc2 * 32 + c] = s;
    }
}

// ---------------------------------------------------------------------------
// fc: (g_pp/1024) [1024,128] @ fc_w.T + fc_b, * mask -> g_h1 [1024,256]
// ---------------------------------------------------------------------------
#define FC_SMEM_BYTES ((128 * 256 + 8 * 128) * 4)

__global__ void __launch_bounds__(256) fc_kernel(const float* __restrict__ fcw,
                                                 const float* __restrict__ fcb,
                                                 const float* __restrict__ mask) {
    extern __shared__ __align__(16) float smf[];
    float* ws = smf;
    float* ps = smf + 128 * 256;
    const int row0 = blockIdx.x * 8, tid = threadIdx.x;

    for (int i = tid; i < 128 * 256; i += 256) {
        int o = i >> 7, d = i & 127;
        ws[d * 256 + o] = fcw[i];
    }
    for (int i = tid; i < 8 * 128; i += 256)
        ps[i] = g_pp[row0 * 128 + i] * (1.f / 1024.f);
    __syncthreads();

    const int o = tid;
    float acc[8];
    float bb = fcb[o];
#pragma unroll
    for (int rr = 0; rr < 8; rr++) acc[rr] = bb;
    for (int d = 0; d < 128; d++) {
        float wv = ws[d * 256 + o];
#pragma unroll
        for (int rr = 0; rr < 8; rr++) acc[rr] = fmaf(ps[rr * 128 + d], wv, acc[rr]);
    }
#pragma unroll
    for (int rr = 0; rr < 8; rr++) {
        int row = row0 + rr;
        g_h1[row * 256 + o] = acc[rr] * mask[row];
    }
}

// ---------------------------------------------------------------------------
// SAGE layer: grid (32 b, 4 node-segments of 8)
// ---------------------------------------------------------------------------
#define SAGE_SMEM_BYTES (32 * 256 * 2 * 4)

template <int OUTD, bool RELU, bool FROM_H1>
__global__ void __launch_bounds__(256) sage_kernel(const float* __restrict__ lw,
                                                   const float* __restrict__ lb,
                                                   const float* __restrict__ rw,
                                                   float* __restrict__ out) {
    extern __shared__ __align__(16) float sms[];  // [n=32][d=256][{agg,h}]
    const int b = blockIdx.x, tid = threadIdx.x;
    const int n0 = blockIdx.y * 8;
    const float* hb = (FROM_H1 ? g_h1 : g_h2) + b * 32 * 256;

    for (int i = tid; i < 32 * 256; i += 256) {
        int nn = i >> 8, d = i & 255;
        sms[(nn * 256 + d) * 2 + 1] = hb[i];
    }
    __syncthreads();
    {
        const int d = tid;
        float s = 0.f;
#pragma unroll
        for (int nn = 0; nn < 32; nn++) s += sms[(nn * 256 + d) * 2 + 1];
#pragma unroll
        for (int nn = 0; nn < 32; nn++) {
            float hv = sms[(nn * 256 + d) * 2 + 1];
            sms[(nn * 256 + d) * 2] = (s - hv) * (1.f / 31.f);
        }
    }
    __syncthreads();

    const int o = tid;
    if (o < OUTD) {
        float acc[8];
        float bb = lb[o];
#pragma unroll
        for (int nn = 0; nn < 8; nn++) acc[nn] = bb;
        for (int d = 0; d < 256; d++) {
            float wl = lw[o * 256 + d];
            float wr = rw[o * 256 + d];
#pragma unroll
            for (int nn = 0; nn < 8; nn++) {
                float2 v = *(const float2*)&sms[((n0 + nn) * 256 + d) * 2];
                acc[nn] += v.x * wl + v.y * wr;
            }
        }
#pragma unroll
        for (int nn = 0; nn < 8; nn++) {
            float r = acc[nn];
            if (RELU) r = fmaxf(r, 0.f);
            if (OUTD == 256)
                g_h2[(b * 32 + n0 + nn) * 256 + o] = r;
            else
                out[(b * 32 + n0 + nn) * OUTD + o] = r;
        }
    }
}

// ---------------------------------------------------------------------------
extern "C" void kernel_launch(void* const* d_in, const int* in_sizes, int n_in,
                              void* d_out, int out_size) {
    const float* x    = (const float*)d_in[0];
    const float* mask = (const float*)d_in[1];
    const float* c1w  = (const float*)d_in[2];
    const float* c1b  = (const float*)d_in[3];
    const float* c2w  = (const float*)d_in[4];
    const float* c2b  = (const float*)d_in[5];
    const float* fcw  = (const float*)d_in[6];
    const float* fcb  = (const float*)d_in[7];
    const float* s1lw = (const float*)d_in[8];
    const float* s1lb = (const float*)d_in[9];
    const float* s1rw = (const float*)d_in[10];
    const float* s2lw = (const float*)d_in[11];
    const float* s2lb = (const float*)d_in[12];
    const float* s2rw = (const float*)d_in[13];
    float* out = (float*)d_out;

    cudaFuncSetAttribute(conv2_mma, cudaFuncAttributeMaxDynamicSharedMemorySize,
                         C2_SMEM);
    cudaFuncSetAttribute(fc_kernel, cudaFuncAttributeMaxDynamicSharedMemorySize,
                         FC_SMEM_BYTES);
    cudaFuncSetAttribute(sage_kernel<256, true, true>,
                         cudaFuncAttributeMaxDynamicSharedMemorySize, SAGE_SMEM_BYTES);
    cudaFuncSetAttribute(sage_kernel<128, false, false>,
                         cudaFuncAttributeMaxDynamicSharedMemorySize, SAGE_SMEM_BYTES);

    prep_w<<<288, 256>>>(c2w);
    conv1_kernel<<<1024, 256>>>(x, c1w, c1b);
    conv2_mma<<<dim3(2, 1024), 256, C2_SMEM>>>(c2b);
    fc_kernel<<<128, 256, FC_SMEM_BYTES>>>(fcw, fcb, mask);
    sage_kernel<256, true, true>
        <<<dim3(32, 4), 256, SAGE_SMEM_BYTES>>>(s1lw, s1lb, s1rw, out);
    sage_kernel<128, false, false>
        <<<dim3(32, 4), 256, SAGE_SMEM_BYTES>>>(s2lw, s2lb, s2rw, out);
}

// round 7
// speedup vs baseline: 7.0732x; 1.4238x over previous
#include <cuda_runtime.h>
#include <cuda_fp16.h>
#include <cstdint>

// ===========================================================================
// GraphSageNet GB300 (sm_103a harness, base sm_103 ptx target) — round 6.
// conv2: ldmatrix + mma.sync m16n8k16 fp16, SINGLE pass (weights rounded to
// fp16; analysis: rel err ~2.8e-4 ≪ 1e-3 gate), 9 live px-tiles,
// double-buffered cp.async slabs, fused bias+relu+avgpool epilogue.
// Fallback if gate fails: R5 two-pass (rel_err 5.2e-6, 1199 us).
// ===========================================================================

#define NPAD 1280                      // padded px slots per image (34*34=1156)
#define GUARD 64
#define ROWS_TOTAL (GUARD + 1024 * NPAD + GUARD)

// scratch (__device__ globals, zero-init at load; pads never written)
__device__ __align__(16) __half g_act[(size_t)ROWS_TOTAL * 64];
__device__ __align__(16) __half g_wh[2 * 9 * 4096];  // [ocg][s][64oc x 128B] SW128
__device__ __align__(16) float g_pp[1024 * 128];
__device__ __align__(16) float g_h1[1024 * 256];
__device__ __align__(16) float g_h2[1024 * 256];

// ------------------------------- helpers -----------------------------------
__device__ __forceinline__ uint32_t smem_u32(const void* p) {
    uint32_t a;
    asm("{ .reg .u64 t; cvta.to.shared.u64 t, %1; cvt.u32.u64 %0, t; }"
        : "=r"(a) : "l"(p));
    return a;
}
__device__ __forceinline__ void ldsm4(uint32_t r[4], uint32_t addr) {
    asm volatile("ldmatrix.sync.aligned.m8n8.x4.shared.b16 {%0,%1,%2,%3}, [%4];"
                 : "=r"(r[0]), "=r"(r[1]), "=r"(r[2]), "=r"(r[3]) : "r"(addr));
}
__device__ __forceinline__ void mma16816(float* d, const uint32_t a[4],
                                         uint32_t b0, uint32_t b1) {
    asm volatile(
        "mma.sync.aligned.m16n8k16.row.col.f32.f16.f16.f32 "
        "{%0,%1,%2,%3}, {%4,%5,%6,%7}, {%8,%9}, {%0,%1,%2,%3};"
        : "+f"(d[0]), "+f"(d[1]), "+f"(d[2]), "+f"(d[3])
        : "r"(a[0]), "r"(a[1]), "r"(a[2]), "r"(a[3]), "r"(b0), "r"(b1));
}
#define CPA16(dst, src) \
    asm volatile("cp.async.cg.shared.global [%0], [%1], 16;" \
                 :: "r"(dst), "l"(src) : "memory")
#define CPA_COMMIT() asm volatile("cp.async.commit_group;" ::: "memory")

// ---------------------------------------------------------------------------
// prep_w: conv2 weights -> fp16, SW128-swizzled [ocg 2][s 9][64 x 128B]
// ---------------------------------------------------------------------------
__global__ void prep_w(const float* __restrict__ w) {
    int idx = blockIdx.x * 256 + threadIdx.x;
    if (idx >= 128 * 64 * 9) return;
    int s = idx % 9, t = idx / 9;
    int ic = t % 64, oc = t / 64;
    float v = w[oc * 576 + ic * 9 + s];
    int ocg = oc >> 6, ocl = oc & 63;
    uint32_t off = (uint32_t)(ocl * 128 + ic * 2);
    uint32_t sw = off ^ ((off >> 3) & 0x70);
    uint32_t base = ((uint32_t)ocg * 9 + (uint32_t)s) * 8192u;
    *(__half*)((char*)g_wh + base + sw) = __float2half_rn(v);
}

// ---------------------------------------------------------------------------
// conv1: [1024,3,32,32] -> relu -> fp16, padded px-major [px][64 ic]
// ---------------------------------------------------------------------------
__global__ void __launch_bounds__(256) conv1_kernel(const float* __restrict__ x,
                                                    const float* __restrict__ w,
                                                    const float* __restrict__ b) {
    __shared__ __align__(16) float ws[27 * 64];
    __shared__ __align__(16) float xs[3 * 34 * 35];

    const int n = blockIdx.x, tid = threadIdx.x;

    for (int i = tid; i < 3 * 34 * 35; i += 256) xs[i] = 0.f;
    for (int i = tid; i < 64 * 27; i += 256) {
        int oc = i / 27, k = i % 27;
        ws[k * 64 + oc] = w[i];
    }
    __syncthreads();
    const float* xin = x + n * 3072;
    for (int i = tid; i < 3072; i += 256) {
        int ic = i >> 10, r = (i >> 5) & 31, c = i & 31;
        xs[ic * (34 * 35) + (r + 1) * 35 + (c + 1)] = xin[i];
    }
    __syncthreads();

    const int ocq = tid >> 5, oc0 = ocq * 8;
    float bias[8];
#pragma unroll
    for (int j = 0; j < 8; j++) bias[j] = b[oc0 + j];

    for (int it = 0; it < 4; it++) {
        int pg = it * 32 + (tid & 31);
        int row = pg >> 2, colb = (pg & 3) * 8;
        float acc[8][8];
#pragma unroll
        for (int j = 0; j < 8; j++)
#pragma unroll
            for (int p = 0; p < 8; p++) acc[j][p] = bias[j];

#pragma unroll
        for (int ic = 0; ic < 3; ic++)
#pragma unroll
            for (int kr = 0; kr < 3; kr++) {
                int base = ic * (34 * 35) + (row + kr) * 35 + colb;
                float in10[10];
#pragma unroll
                for (int q = 0; q < 10; q++) in10[q] = xs[base + q];
#pragma unroll
                for (int kc = 0; kc < 3; kc++) {
                    int k = ic * 9 + kr * 3 + kc;
                    float4 w0 = *(const float4*)&ws[k * 64 + oc0];
                    float4 w1 = *(const float4*)&ws[k * 64 + oc0 + 4];
                    float wv[8] = {w0.x, w0.y, w0.z, w0.w, w1.x, w1.y, w1.z, w1.w};
#pragma unroll
                    for (int j = 0; j < 8; j++)
#pragma unroll
                        for (int p = 0; p < 8; p++)
                            acc[j][p] = fmaf(wv[j], in10[kc + p], acc[j][p]);
                }
            }
#pragma unroll
        for (int p = 0; p < 8; p++) {
            int col = colb + p;
            size_t pxa = (size_t)GUARD + (size_t)n * NPAD + (row + 1) * 34 + (col + 1);
            uint32_t q[4];
#pragma unroll
            for (int pr = 0; pr < 4; pr++) {
                __half h0 = __float2half_rn(fmaxf(acc[2 * pr][p], 0.f));
                __half h1 = __float2half_rn(fmaxf(acc[2 * pr + 1][p], 0.f));
                q[pr] = (uint32_t)__half_as_ushort(h0) |
                        ((uint32_t)__half_as_ushort(h1) << 16);
            }
            *(uint4*)&g_act[pxa * 64 + oc0] = make_uint4(q[0], q[1], q[2], q[3]);
        }
    }
}

// ---------------------------------------------------------------------------
// conv2 via mma.sync: grid (2 ocg, 1024 n), 8 warps, 1 CTA/SM.
// warp tile 32px x 32oc; 9 px-tiles of 128; single fp16 pass.
// smem: Wh 73728 | slab x2 bufs 50688 | bias 256 | red 1024
// ---------------------------------------------------------------------------
#define SM_WH 0
#define SM_SLAB 73728
#define SLAB_BYTES 25344
#define SM_BIAS 124416
#define SM_RED 124672
#define C2_SMEM 125696

__global__ void __launch_bounds__(256, 1) conv2_mma(const float* __restrict__ bias) {
    extern __shared__ __align__(1024) char smc[];
    const uint32_t smb = smem_u32(smc);
    const int tid = threadIdx.x, wid = tid >> 5, lane = tid & 31;
    const int ocg = blockIdx.x, n = blockIdx.y;
    const int pxw = wid & 3, ocw = wid >> 2;

    const size_t img_base = (size_t)GUARD + (size_t)n * NPAD;
    const uint4* ga = (const uint4*)g_act;

    // ---- stage weights (pre-swizzled) + slab 0, one cp.async group ----
    {
        const uint4* srcH = (const uint4*)((const char*)g_wh + (size_t)ocg * 73728);
        for (int i = tid; i < 4608; i += 256)
            CPA16(smb + SM_WH + i * 16, srcH + i);
        size_t gbase = (img_base - 35) * 8;
        for (int i = tid; i < 1584; i += 256) {
            int r = i >> 3, j = i & 7;
            uint32_t d = (uint32_t)(r * 128) +
                         (((uint32_t)(j * 16)) ^ ((uint32_t)((r & 7) << 4)));
            CPA16(smb + SM_SLAB + d, ga + gbase + (size_t)r * 8 + j);
        }
        CPA_COMMIT();
    }
    if (tid < 64) ((float*)(smc + SM_BIAS))[tid] = bias[ocg * 64 + tid];

    const int l15 = lane & 15;
    const uint32_t lk = (uint32_t)((lane >> 4) * 16);
    const int rB0 = ocw * 32 + l15, rB1 = rB0 + 16;
    const uint32_t swB0 = (uint32_t)((rB0 & 7) << 4);
    const uint32_t swB1 = (uint32_t)((rB1 & 7) << 4);

    float b8[8];
#pragma unroll
    for (int nt = 0; nt < 4; nt++)
#pragma unroll
        for (int bb = 0; bb < 2; bb++)
            b8[nt * 2 + bb] = bias[ocg * 64 + ocw * 32 + nt * 8 + (lane & 3) * 2 + bb];

    float psum[8];
#pragma unroll
    for (int i = 0; i < 8; i++) psum[i] = 0.f;

    asm volatile("cp.async.wait_group 0;" ::: "memory");
    __syncthreads();

    for (int t = 0; t < 9; t++) {
        // issue next slab into the other buffer (prev compute there is done)
        if (t < 8) {
            size_t gbase = (img_base + (size_t)(t + 1) * 128 - 35) * 8;
            uint32_t sbase = smb + SM_SLAB + (uint32_t)(((t + 1) & 1) * SLAB_BYTES);
            for (int i = tid; i < 1584; i += 256) {
                int r = i >> 3, j = i & 7;
                uint32_t d = (uint32_t)(r * 128) +
                             (((uint32_t)(j * 16)) ^ ((uint32_t)((r & 7) << 4)));
                CPA16(sbase + d, ga + gbase + (size_t)r * 8 + j);
            }
            CPA_COMMIT();
            asm volatile("cp.async.wait_group 1;" ::: "memory");
        } else {
            asm volatile("cp.async.wait_group 0;" ::: "memory");
        }
        __syncthreads();

        const uint32_t sbA = smb + SM_SLAB + (uint32_t)((t & 1) * SLAB_BYTES);
        float acc[2][4][4];
#pragma unroll
        for (int mt = 0; mt < 2; mt++)
#pragma unroll
            for (int nt = 0; nt < 4; nt++)
#pragma unroll
                for (int rg = 0; rg < 4; rg++) acc[mt][nt][rg] = 0.f;

        for (int s = 0; s < 9; s++) {
            const int doff = (s / 3 - 1) * 34 + (s % 3 - 1);
            const int rA0 = 35 + doff + pxw * 32 + l15;
            const int rA1 = rA0 + 16;
            const uint32_t swA0 = (uint32_t)((rA0 & 7) << 4);
            const uint32_t swA1 = (uint32_t)((rA1 & 7) << 4);
            const uint32_t wt = (uint32_t)(s * 8192);
#pragma unroll
            for (int k = 0; k < 4; k++) {
                const uint32_t kb = (uint32_t)(k * 32) + lk;
                uint32_t a0[4], a1[4], bh0[4], bh1[4];
                ldsm4(a0, sbA + (uint32_t)(rA0 * 128) + (kb ^ swA0));
                ldsm4(a1, sbA + (uint32_t)(rA1 * 128) + (kb ^ swA1));
                ldsm4(bh0, smb + SM_WH + wt + (uint32_t)(rB0 * 128) + (kb ^ swB0));
                ldsm4(bh1, smb + SM_WH + wt + (uint32_t)(rB1 * 128) + (kb ^ swB1));
                mma16816(acc[0][0], a0, bh0[0], bh0[2]);
                mma16816(acc[0][1], a0, bh0[1], bh0[3]);
                mma16816(acc[0][2], a0, bh1[0], bh1[2]);
                mma16816(acc[0][3], a0, bh1[1], bh1[3]);
                mma16816(acc[1][0], a1, bh0[0], bh0[2]);
                mma16816(acc[1][1], a1, bh0[1], bh0[3]);
                mma16816(acc[1][2], a1, bh1[0], bh1[2]);
                mma16816(acc[1][3], a1, bh1[1], bh1[3]);
            }
        }

        // ---- epilogue: bias + relu + masked pool accumulate ----
        bool inter[2][2];
#pragma unroll
        for (int mt = 0; mt < 2; mt++)
#pragma unroll
            for (int hh = 0; hh < 2; hh++) {
                int pl = t * 128 + pxw * 32 + mt * 16 + (lane >> 2) + hh * 8;
                int rr = pl / 34, cc = pl - rr * 34;
                inter[mt][hh] =
                    (pl < 1156) & (rr >= 1) & (rr <= 32) & (cc >= 1) & (cc <= 32);
            }
#pragma unroll
        for (int mt = 0; mt < 2; mt++)
#pragma unroll
            for (int nt = 0; nt < 4; nt++)
#pragma unroll
                for (int rg = 0; rg < 4; rg++) {
                    float v = fmaxf(acc[mt][nt][rg] + b8[nt * 2 + (rg & 1)], 0.f);
                    if (inter[mt][rg >> 1]) psum[nt * 2 + (rg & 1)] += v;
                }
        __syncthreads();  // compute done before next-next slab overwrites buffer
    }

    // ---- reduce: xor over lane bits 2..4 sums px-rows within warp ----
#pragma unroll
    for (int off = 4; off <= 16; off <<= 1)
#pragma unroll
        for (int i = 0; i < 8; i++)
            psum[i] += __shfl_xor_sync(0xffffffffu, psum[i], off);

    float* red = (float*)(smc + SM_RED);   // [8 warps][32 cols]
    if (lane < 4) {
#pragma unroll
        for (int nt = 0; nt < 4; nt++)
#pragma unroll
            for (int bb = 0; bb < 2; bb++)
                red[wid * 32 + nt * 8 + lane * 2 + bb] = psum[nt * 2 + bb];
    }
    __syncthreads();
    if (tid < 64) {
        int oc2 = tid >> 5, c = tid & 31;
        float s = 0.f;
#pragma unroll
        for (int p = 0; p < 4; p++) s += red[(oc2 * 4 + p) * 32 + c];
        g_pp[n * 128 + ocg * 64 + oc2 * 32 + c] = s;
    }
}

// ---------------------------------------------------------------------------
// fc: (g_pp/1024) [1024,128] @ fc_w.T + fc_b, * mask -> g_h1 [1024,256]
// ---------------------------------------------------------------------------
#define FC_SMEM_BYTES ((128 * 256 + 8 * 128) * 4)

__global__ void __launch_bounds__(256) fc_kernel(const float* __restrict__ fcw,
                                                 const float* __restrict__ fcb,
                                                 const float* __restrict__ mask) {
    extern __shared__ __align__(16) float smf[];
    float* ws = smf;
    float* ps = smf + 128 * 256;
    const int row0 = blockIdx.x * 8, tid = threadIdx.x;

    for (int i = tid; i < 128 * 256; i += 256) {
        int o = i >> 7, d = i & 127;
        ws[d * 256 + o] = fcw[i];
    }
    for (int i = tid; i < 8 * 128; i += 256)
        ps[i] = g_pp[row0 * 128 + i] * (1.f / 1024.f);
    __syncthreads();

    const int o = tid;
    float acc[8];
    float bb = fcb[o];
#pragma unroll
    for (int rr = 0; rr < 8; rr++) acc[rr] = bb;
    for (int d = 0; d < 128; d++) {
        float wv = ws[d * 256 + o];
#pragma unroll
        for (int rr = 0; rr < 8; rr++) acc[rr] = fmaf(ps[rr * 128 + d], wv, acc[rr]);
    }
#pragma unroll
    for (int rr = 0; rr < 8; rr++) {
        int row = row0 + rr;
        g_h1[row * 256 + o] = acc[rr] * mask[row];
    }
}

// ---------------------------------------------------------------------------
// SAGE layer: grid (32 b, 4 node-segments of 8)
// ---------------------------------------------------------------------------
#define SAGE_SMEM_BYTES (32 * 256 * 2 * 4)

template <int OUTD, bool RELU, bool FROM_H1>
__global__ void __launch_bounds__(256) sage_kernel(const float* __restrict__ lw,
                                                   const float* __restrict__ lb,
                                                   const float* __restrict__ rw,
                                                   float* __restrict__ out) {
    extern __shared__ __align__(16) float sms[];  // [n=32][d=256][{agg,h}]
    const int b = blockIdx.x, tid = threadIdx.x;
    const int n0 = blockIdx.y * 8;
    const float* hb = (FROM_H1 ? g_h1 : g_h2) + b * 32 * 256;

    for (int i = tid; i < 32 * 256; i += 256) {
        int nn = i >> 8, d = i & 255;
        sms[(nn * 256 + d) * 2 + 1] = hb[i];
    }
    __syncthreads();
    {
        const int d = tid;
        float s = 0.f;
#pragma unroll
        for (int nn = 0; nn < 32; nn++) s += sms[(nn * 256 + d) * 2 + 1];
#pragma unroll
        for (int nn = 0; nn < 32; nn++) {
            float hv = sms[(nn * 256 + d) * 2 + 1];
            sms[(nn * 256 + d) * 2] = (s - hv) * (1.f / 31.f);
        }
    }
    __syncthreads();

    const int o = tid;
    if (o < OUTD) {
        float acc[8];
        float bb = lb[o];
#pragma unroll
        for (int nn = 0; nn < 8; nn++) acc[nn] = bb;
        for (int d = 0; d < 256; d++) {
            float wl = lw[o * 256 + d];
            float wr = rw[o * 256 + d];
#pragma unroll
            for (int nn = 0; nn < 8; nn++) {
                float2 v = *(const float2*)&sms[((n0 + nn) * 256 + d) * 2];
                acc[nn] += v.x * wl + v.y * wr;
            }
        }
#pragma unroll
        for (int nn = 0; nn < 8; nn++) {
            float r = acc[nn];
            if (RELU) r = fmaxf(r, 0.f);
            if (OUTD == 256)
                g_h2[(b * 32 + n0 + nn) * 256 + o] = r;
            else
                out[(b * 32 + n0 + nn) * OUTD + o] = r;
        }
    }
}

// ---------------------------------------------------------------------------
extern "C" void kernel_launch(void* const* d_in, const int* in_sizes, int n_in,
                              void* d_out, int out_size) {
    const float* x    = (const float*)d_in[0];
    const float* mask = (const float*)d_in[1];
    const float* c1w  = (const float*)d_in[2];
    const float* c1b  = (const float*)d_in[3];
    const float* c2w  = (const float*)d_in[4];
    const float* c2b  = (const float*)d_in[5];
    const float* fcw  = (const float*)d_in[6];
    const float* fcb  = (const float*)d_in[7];
    const float* s1lw = (const float*)d_in[8];
    const float* s1lb = (const float*)d_in[9];
    const float* s1rw = (const float*)d_in[10];
    const float* s2lw = (const float*)d_in[11];
    const float* s2lb = (const float*)d_in[12];
    const float* s2rw = (const float*)d_in[13];
    float* out = (float*)d_out;

    cudaFuncSetAttribute(conv2_mma, cudaFuncAttributeMaxDynamicSharedMemorySize,
                         C2_SMEM);
    cudaFuncSetAttribute(fc_kernel, cudaFuncAttributeMaxDynamicSharedMemorySize,
                         FC_SMEM_BYTES);
    cudaFuncSetAttribute(sage_kernel<256, true, true>,
                         cudaFuncAttributeMaxDynamicSharedMemorySize, SAGE_SMEM_BYTES);
    cudaFuncSetAttribute(sage_kernel<128, false, false>,
                         cudaFuncAttributeMaxDynamicSharedMemorySize, SAGE_SMEM_BYTES);

    prep_w<<<288, 256>>>(c2w);
    conv1_kernel<<<1024, 256>>>(x, c1w, c1b);
    conv2_mma<<<dim3(2, 1024), 256, C2_SMEM>>>(c2b);
    fc_kernel<<<128, 256, FC_SMEM_BYTES>>>(fcw, fcb, mask);
    sage_kernel<256, true, true>
        <<<dim3(32, 4), 256, SAGE_SMEM_BYTES>>>(s1lw, s1lb, s1rw, out);
    sage_kernel<128, false, false>
        <<<dim3(32, 4), 256, SAGE_SMEM_BYTES>>>(s2lw, s2lb, s2rw, out);
}

// round 8
// speedup vs baseline: 7.4882x; 1.0587x over previous
#include <cuda_runtime.h>
#include <cuda_fp16.h>
#include <cstdint>

// ===========================================================================
// GraphSageNet GB300 — round 7.
// conv2: single-pass fp16 mma.sync (unchanged from R6, ~590us, HMMA floor).
// NEW: conv1 uses packed fma.rn.f32x2 (2x fp32 FMA rate).
// NEW: fc+sage1+sage2 fused into ONE head kernel per batch, using the fold
//      sage(h) = h @ (rw - lw/31)^T + [(cs@lw^T)/31 + lb]   (halves GEMM work)
// ===========================================================================

#define NPAD 1280
#define GUARD 64
#define ROWS_TOTAL (GUARD + 1024 * NPAD + GUARD)

__device__ __align__(16) __half g_act[(size_t)ROWS_TOTAL * 64];
__device__ __align__(16) __half g_wh[2 * 9 * 4096];
__device__ __align__(16) float g_pp[1024 * 128];
// folded sage weights (transposed [d][o]) + lw transposed
__device__ __align__(16) float g_w21t[256 * 256];
__device__ __align__(16) float g_l1t [256 * 256];
__device__ __align__(16) float g_w22t[256 * 128];
__device__ __align__(16) float g_l2t [256 * 128];

// ------------------------------- helpers -----------------------------------
__device__ __forceinline__ uint32_t smem_u32(const void* p) {
    uint32_t a;
    asm("{ .reg .u64 t; cvta.to.shared.u64 t, %1; cvt.u32.u64 %0, t; }"
        : "=r"(a) : "l"(p));
    return a;
}
__device__ __forceinline__ void ldsm4(uint32_t r[4], uint32_t addr) {
    asm volatile("ldmatrix.sync.aligned.m8n8.x4.shared.b16 {%0,%1,%2,%3}, [%4];"
                 : "=r"(r[0]), "=r"(r[1]), "=r"(r[2]), "=r"(r[3]) : "r"(addr));
}
__device__ __forceinline__ void mma16816(float* d, const uint32_t a[4],
                                         uint32_t b0, uint32_t b1) {
    asm volatile(
        "mma.sync.aligned.m16n8k16.row.col.f32.f16.f16.f32 "
        "{%0,%1,%2,%3}, {%4,%5,%6,%7}, {%8,%9}, {%0,%1,%2,%3};"
        : "+f"(d[0]), "+f"(d[1]), "+f"(d[2]), "+f"(d[3])
        : "r"(a[0]), "r"(a[1]), "r"(a[2]), "r"(a[3]), "r"(b0), "r"(b1));
}
#define CPA16(dst, src) \
    asm volatile("cp.async.cg.shared.global [%0], [%1], 16;" \
                 :: "r"(dst), "l"(src) : "memory")
#define CPA_COMMIT() asm volatile("cp.async.commit_group;" ::: "memory")

__device__ __forceinline__ unsigned long long pack2(float lo, float hi) {
    unsigned long long d;
    asm("mov.b64 %0, {%1, %2};" : "=l"(d)
        : "r"(__float_as_uint(lo)), "r"(__float_as_uint(hi)));
    return d;
}
__device__ __forceinline__ void unpack2(unsigned long long v, float& lo, float& hi) {
    unsigned a, b;
    asm("mov.b64 {%0, %1}, %2;" : "=r"(a), "=r"(b) : "l"(v));
    lo = __uint_as_float(a); hi = __uint_as_float(b);
}
__device__ __forceinline__ void fma2(unsigned long long& d, unsigned long long a,
                                     unsigned long long b, unsigned long long c) {
    asm("fma.rn.f32x2 %0, %1, %2, %3;" : "=l"(d) : "l"(a), "l"(b), "l"(c));
}

// ---------------------------------------------------------------------------
// prep_w: conv2 weights -> fp16, SW128-swizzled [ocg 2][s 9][64 x 128B]
// ---------------------------------------------------------------------------
__global__ void prep_w(const float* __restrict__ w) {
    int idx = blockIdx.x * 256 + threadIdx.x;
    if (idx >= 128 * 64 * 9) return;
    int s = idx % 9, t = idx / 9;
    int ic = t % 64, oc = t / 64;
    float v = w[oc * 576 + ic * 9 + s];
    int ocg = oc >> 6, ocl = oc & 63;
    uint32_t off = (uint32_t)(ocl * 128 + ic * 2);
    uint32_t sw = off ^ ((off >> 3) & 0x70);
    uint32_t base = ((uint32_t)ocg * 9 + (uint32_t)s) * 8192u;
    *(__half*)((char*)g_wh + base + sw) = __float2half_rn(v);
}

// ---------------------------------------------------------------------------
// prep_sage: W2 = rw - lw/31 (transposed [d][o]) + lw transposed
// ---------------------------------------------------------------------------
__global__ void prep_sage(const float* __restrict__ s1lw,
                          const float* __restrict__ s1rw,
                          const float* __restrict__ s2lw,
                          const float* __restrict__ s2rw) {
    const float C = 1.f / 31.f;
    int idx = blockIdx.x * 256 + threadIdx.x;
    if (idx < 65536) {
        int o = idx >> 8, d = idx & 255;
        float l = s1lw[idx];
        g_w21t[d * 256 + o] = s1rw[idx] - C * l;
        g_l1t [d * 256 + o] = l;
    } else if (idx < 98304) {
        int j = idx - 65536;
        int o = j >> 8, d = j & 255;
        float l = s2lw[j];
        g_w22t[d * 128 + o] = s2rw[j] - C * l;
        g_l2t [d * 128 + o] = l;
    }
}

// ---------------------------------------------------------------------------
// conv1: [1024,3,32,32] -> relu -> fp16 padded px-major; packed f32x2 FMA
// ---------------------------------------------------------------------------
__global__ void __launch_bounds__(256) conv1_kernel(const float* __restrict__ x,
                                                    const float* __restrict__ w,
                                                    const float* __restrict__ b) {
    __shared__ __align__(16) float ws[27 * 64];
    __shared__ __align__(16) float xs[3 * 34 * 35];

    const int n = blockIdx.x, tid = threadIdx.x;

    for (int i = tid; i < 3 * 34 * 35; i += 256) xs[i] = 0.f;
    for (int i = tid; i < 64 * 27; i += 256) {
        int oc = i / 27, k = i % 27;
        ws[k * 64 + oc] = w[i];
    }
    __syncthreads();
    const float* xin = x + n * 3072;
    for (int i = tid; i < 3072; i += 256) {
        int ic = i >> 10, r = (i >> 5) & 31, c = i & 31;
        xs[ic * (34 * 35) + (r + 1) * 35 + (c + 1)] = xin[i];
    }
    __syncthreads();

    const int ocq = tid >> 5, oc0 = ocq * 8;
    unsigned long long bp[8];
#pragma unroll
    for (int j = 0; j < 8; j++) {
        float bv = b[oc0 + j];
        bp[j] = pack2(bv, bv);
    }

    for (int it = 0; it < 4; it++) {
        int pg = it * 32 + (tid & 31);
        int row = pg >> 2, colb = (pg & 3) * 8;
        unsigned long long acc[8][4];
#pragma unroll
        for (int j = 0; j < 8; j++)
#pragma unroll
            for (int t = 0; t < 4; t++) acc[j][t] = bp[j];

#pragma unroll
        for (int ic = 0; ic < 3; ic++)
#pragma unroll
            for (int kr = 0; kr < 3; kr++) {
                int base = ic * (34 * 35) + (row + kr) * 35 + colb;
                float in10[10];
#pragma unroll
                for (int q = 0; q < 10; q++) in10[q] = xs[base + q];
#pragma unroll
                for (int kc = 0; kc < 3; kc++) {
                    int k = ic * 9 + kr * 3 + kc;
                    float4 w0 = *(const float4*)&ws[k * 64 + oc0];
                    float4 w1 = *(const float4*)&ws[k * 64 + oc0 + 4];
                    float wv[8] = {w0.x, w0.y, w0.z, w0.w, w1.x, w1.y, w1.z, w1.w};
                    unsigned long long ip[4];
#pragma unroll
                    for (int t = 0; t < 4; t++)
                        ip[t] = pack2(in10[kc + 2 * t], in10[kc + 2 * t + 1]);
#pragma unroll
                    for (int j = 0; j < 8; j++) {
                        unsigned long long wp = pack2(wv[j], wv[j]);
#pragma unroll
                        for (int t = 0; t < 4; t++) fma2(acc[j][t], wp, ip[t], acc[j][t]);
                    }
                }
            }
#pragma unroll
        for (int p = 0; p < 8; p++) {
            int col = colb + p;
            size_t pxa = (size_t)GUARD + (size_t)n * NPAD + (row + 1) * 34 + (col + 1);
            uint32_t q[4];
#pragma unroll
            for (int pr = 0; pr < 4; pr++) {
                float a0l, a0h, a1l, a1h;
                unpack2(acc[2 * pr][p >> 1], a0l, a0h);
                unpack2(acc[2 * pr + 1][p >> 1], a1l, a1h);
                float v0 = (p & 1) ? a0h : a0l;
                float v1 = (p & 1) ? a1h : a1l;
                __half h0 = __float2half_rn(fmaxf(v0, 0.f));
                __half h1 = __float2half_rn(fmaxf(v1, 0.f));
                q[pr] = (uint32_t)__half_as_ushort(h0) |
                        ((uint32_t)__half_as_ushort(h1) << 16);
            }
            *(uint4*)&g_act[pxa * 64 + oc0] = make_uint4(q[0], q[1], q[2], q[3]);
        }
    }
}

// ---------------------------------------------------------------------------
// conv2 via mma.sync (unchanged from R6)
// ---------------------------------------------------------------------------
#define SM_WH 0
#define SM_SLAB 73728
#define SLAB_BYTES 25344
#define SM_BIAS 124416
#define SM_RED 124672
#define C2_SMEM 125696

__global__ void __launch_bounds__(256, 1) conv2_mma(const float* __restrict__ bias) {
    extern __shared__ __align__(1024) char smc[];
    const uint32_t smb = smem_u32(smc);
    const int tid = threadIdx.x, wid = tid >> 5, lane = tid & 31;
    const int ocg = blockIdx.x, n = blockIdx.y;
    const int pxw = wid & 3, ocw = wid >> 2;

    const size_t img_base = (size_t)GUARD + (size_t)n * NPAD;
    const uint4* ga = (const uint4*)g_act;

    {
        const uint4* srcH = (const uint4*)((const char*)g_wh + (size_t)ocg * 73728);
        for (int i = tid; i < 4608; i += 256)
            CPA16(smb + SM_WH + i * 16, srcH + i);
        size_t gbase = (img_base - 35) * 8;
        for (int i = tid; i < 1584; i += 256) {
            int r = i >> 3, j = i & 7;
            uint32_t d = (uint32_t)(r * 128) +
                         (((uint32_t)(j * 16)) ^ ((uint32_t)((r & 7) << 4)));
            CPA16(smb + SM_SLAB + d, ga + gbase + (size_t)r * 8 + j);
        }
        CPA_COMMIT();
    }
    if (tid < 64) ((float*)(smc + SM_BIAS))[tid] = bias[ocg * 64 + tid];

    const int l15 = lane & 15;
    const uint32_t lk = (uint32_t)((lane >> 4) * 16);
    const int rB0 = ocw * 32 + l15, rB1 = rB0 + 16;
    const uint32_t swB0 = (uint32_t)((rB0 & 7) << 4);
    const uint32_t swB1 = (uint32_t)((rB1 & 7) << 4);

    float b8[8];
#pragma unroll
    for (int nt = 0; nt < 4; nt++)
#pragma unroll
        for (int bb = 0; bb < 2; bb++)
            b8[nt * 2 + bb] = bias[ocg * 64 + ocw * 32 + nt * 8 + (lane & 3) * 2 + bb];

    float psum[8];
#pragma unroll
    for (int i = 0; i < 8; i++) psum[i] = 0.f;

    asm volatile("cp.async.wait_group 0;" ::: "memory");
    __syncthreads();

    for (int t = 0; t < 9; t++) {
        if (t < 8) {
            size_t gbase = (img_base + (size_t)(t + 1) * 128 - 35) * 8;
            uint32_t sbase = smb + SM_SLAB + (uint32_t)(((t + 1) & 1) * SLAB_BYTES);
            for (int i = tid; i < 1584; i += 256) {
                int r = i >> 3, j = i & 7;
                uint32_t d = (uint32_t)(r * 128) +
                             (((uint32_t)(j * 16)) ^ ((uint32_t)((r & 7) << 4)));
                CPA16(sbase + d, ga + gbase + (size_t)r * 8 + j);
            }
            CPA_COMMIT();
            asm volatile("cp.async.wait_group 1;" ::: "memory");
        } else {
            asm volatile("cp.async.wait_group 0;" ::: "memory");
        }
        __syncthreads();

        const uint32_t sbA = smb + SM_SLAB + (uint32_t)((t & 1) * SLAB_BYTES);
        float acc[2][4][4];
#pragma unroll
        for (int mt = 0; mt < 2; mt++)
#pragma unroll
            for (int nt = 0; nt < 4; nt++)
#pragma unroll
                for (int rg = 0; rg < 4; rg++) acc[mt][nt][rg] = 0.f;

        for (int s = 0; s < 9; s++) {
            const int doff = (s / 3 - 1) * 34 + (s % 3 - 1);
            const int rA0 = 35 + doff + pxw * 32 + l15;
            const int rA1 = rA0 + 16;
            const uint32_t swA0 = (uint32_t)((rA0 & 7) << 4);
            const uint32_t swA1 = (uint32_t)((rA1 & 7) << 4);
            const uint32_t wt = (uint32_t)(s * 8192);
#pragma unroll
            for (int k = 0; k < 4; k++) {
                const uint32_t kb = (uint32_t)(k * 32) + lk;
                uint32_t a0[4], a1[4], bh0[4], bh1[4];
                ldsm4(a0, sbA + (uint32_t)(rA0 * 128) + (kb ^ swA0));
                ldsm4(a1, sbA + (uint32_t)(rA1 * 128) + (kb ^ swA1));
                ldsm4(bh0, smb + SM_WH + wt + (uint32_t)(rB0 * 128) + (kb ^ swB0));
                ldsm4(bh1, smb + SM_WH + wt + (uint32_t)(rB1 * 128) + (kb ^ swB1));
                mma16816(acc[0][0], a0, bh0[0], bh0[2]);
                mma16816(acc[0][1], a0, bh0[1], bh0[3]);
                mma16816(acc[0][2], a0, bh1[0], bh1[2]);
                mma16816(acc[0][3], a0, bh1[1], bh1[3]);
                mma16816(acc[1][0], a1, bh0[0], bh0[2]);
                mma16816(acc[1][1], a1, bh0[1], bh0[3]);
                mma16816(acc[1][2], a1, bh1[0], bh1[2]);
                mma16816(acc[1][3], a1, bh1[1], bh1[3]);
            }
        }

        bool inter[2][2];
#pragma unroll
        for (int mt = 0; mt < 2; mt++)
#pragma unroll
            for (int hh = 0; hh < 2; hh++) {
                int pl = t * 128 + pxw * 32 + mt * 16 + (lane >> 2) + hh * 8;
                int rr = pl / 34, cc = pl - rr * 34;
                inter[mt][hh] =
                    (pl < 1156) & (rr >= 1) & (rr <= 32) & (cc >= 1) & (cc <= 32);
            }
#pragma unroll
        for (int mt = 0; mt < 2; mt++)
#pragma unroll
            for (int nt = 0; nt < 4; nt++)
#pragma unroll
                for (int rg = 0; rg < 4; rg++) {
                    float v = fmaxf(acc[mt][nt][rg] + b8[nt * 2 + (rg & 1)], 0.f);
                    if (inter[mt][rg >> 1]) psum[nt * 2 + (rg & 1)] += v;
                }
        __syncthreads();
    }

#pragma unroll
    for (int off = 4; off <= 16; off <<= 1)
#pragma unroll
        for (int i = 0; i < 8; i++)
            psum[i] += __shfl_xor_sync(0xffffffffu, psum[i], off);

    float* red = (float*)(smc + SM_RED);
    if (lane < 4) {
#pragma unroll
        for (int nt = 0; nt < 4; nt++)
#pragma unroll
            for (int bb = 0; bb < 2; bb++)
                red[wid * 32 + nt * 8 + lane * 2 + bb] = psum[nt * 2 + bb];
    }
    __syncthreads();
    if (tid < 64) {
        int oc2 = tid >> 5, c = tid & 31;
        float s = 0.f;
#pragma unroll
        for (int p = 0; p < 4; p++) s += red[(oc2 * 4 + p) * 32 + c];
        g_pp[n * 128 + ocg * 64 + oc2 * 32 + c] = s;
    }
}

// ---------------------------------------------------------------------------
// head: fc + mask + sage1(relu) + sage2, one block per batch b (grid 32).
// smem layout (floats):
//  PS  [32][128]                  @0       (16384 B)
//  W   weight stage, 33024 f      @16384   (132096 B)  [d][257] or [d][129]
//  HT  [256 rows][36]             @148480  (36864 B)   xor-swizzled f4 groups
//  H2T [256 rows][36]             @185344  (36864 B)
//  CS  [256]                      @222208  (1024 B)
//  MK  [32]                       @223232  (128 B)
// total 223360 B
// ---------------------------------------------------------------------------
#define HS_PS 0
#define HS_W 16384
#define HS_HT 148480
#define HS_H2T 185344
#define HS_CS 222208
#define HS_MK 223232
#define HEAD_SMEM 223360

__global__ void __launch_bounds__(256, 1) head_kernel(
    const float* __restrict__ fcw, const float* __restrict__ fcb,
    const float* __restrict__ mask,
    const float* __restrict__ s1lb, const float* __restrict__ s2lb,
    float* __restrict__ out) {
    extern __shared__ __align__(16) float sh[];
    float* PS  = sh + HS_PS / 4;
    float* W   = sh + HS_W / 4;
    float* HT  = sh + HS_HT / 4;
    float* H2T = sh + HS_H2T / 4;
    float* CS  = sh + HS_CS / 4;
    float* MK  = sh + HS_MK / 4;

    const int b = blockIdx.x, tid = threadIdx.x;
    const float C = 1.f / 31.f;

    // stage pooled features (scaled) + fc weights transposed [d][257] + mask
    for (int i = tid; i < 32 * 128; i += 256)
        PS[i] = g_pp[b * 32 * 128 + i] * (1.f / 1024.f);
    for (int i = tid; i < 32768; i += 256) {
        int o = i >> 7, d = i & 127;
        W[d * 257 + o] = fcw[i];
    }
    if (tid < 32) MK[tid] = mask[b * 32 + tid];
    __syncthreads();

    const int o = tid;
    const int operm = o & 7;

    // ---- fc: acc[n] = sum_d ps[n][d] * fcw[o][d] ----
    {
        float acc[32];
#pragma unroll
        for (int n = 0; n < 32; n++) acc[n] = 0.f;
        const float4* ps4 = (const float4*)PS;
        for (int d4 = 0; d4 < 32; d4++) {
            float w0 = W[(4 * d4 + 0) * 257 + o];
            float w1 = W[(4 * d4 + 1) * 257 + o];
            float w2 = W[(4 * d4 + 2) * 257 + o];
            float w3 = W[(4 * d4 + 3) * 257 + o];
#pragma unroll
            for (int n = 0; n < 32; n++) {
                float4 p = ps4[n * 32 + d4];
                acc[n] += p.x * w0 + p.y * w1 + p.z * w2 + p.w * w3;
            }
        }
        float bb = fcb[o];
#pragma unroll
        for (int n4 = 0; n4 < 8; n4++) {
            float4 v;
            v.x = (acc[n4 * 4 + 0] + bb) * MK[n4 * 4 + 0];
            v.y = (acc[n4 * 4 + 1] + bb) * MK[n4 * 4 + 1];
            v.z = (acc[n4 * 4 + 2] + bb) * MK[n4 * 4 + 2];
            v.w = (acc[n4 * 4 + 3] + bb) * MK[n4 * 4 + 3];
            *(float4*)&HT[o * 36 + 4 * (n4 ^ operm)] = v;
        }
    }
    __syncthreads();

    // ---- cs[d] = sum_n h[n][d] ----
    {
        float s = 0.f;
#pragma unroll
        for (int g = 0; g < 8; g++) {
            float4 v = *(const float4*)&HT[tid * 36 + 4 * g];
            s += v.x + v.y + v.z + v.w;
        }
        CS[tid] = s;
    }
    __syncthreads();

    // ---- v1[o] = (1/31) * sum_d cs[d]*lw1[o][d]; acc2 = v1 + lb1 ----
    float acc2[32];
    {
        float v = 0.f;
        for (int d = 0; d < 256; d += 4) {
            v += CS[d] * g_l1t[d * 256 + o] + CS[d + 1] * g_l1t[(d + 1) * 256 + o] +
                 CS[d + 2] * g_l1t[(d + 2) * 256 + o] +
                 CS[d + 3] * g_l1t[(d + 3) * 256 + o];
        }
        float init = v * C + s1lb[o];
#pragma unroll
        for (int n = 0; n < 32; n++) acc2[n] = init;
    }

    // ---- sage1 GEMM: acc2[n] += sum_d h[n][d]*W2_1[o][d], 2 chunks ----
    for (int c = 0; c < 2; c++) {
        __syncthreads();
        for (int i = tid; i < 32768; i += 256) {
            int dd = i >> 8, oo = i & 255;
            W[dd * 257 + oo] = g_w21t[(c * 128 + dd) * 256 + oo];
        }
        __syncthreads();
        for (int dd = 0; dd < 128; dd++) {
            int d = c * 128 + dd;
            float w = W[dd * 257 + o];
            int dperm = d & 7;
#pragma unroll
            for (int n4 = 0; n4 < 8; n4++) {
                float4 hv = *(const float4*)&HT[d * 36 + 4 * (n4 ^ dperm)];
                acc2[n4 * 4 + 0] += hv.x * w;
                acc2[n4 * 4 + 1] += hv.y * w;
                acc2[n4 * 4 + 2] += hv.z * w;
                acc2[n4 * 4 + 3] += hv.w * w;
            }
        }
    }
    // relu + store h2
#pragma unroll
    for (int n4 = 0; n4 < 8; n4++) {
        float4 v;
        v.x = fmaxf(acc2[n4 * 4 + 0], 0.f);
        v.y = fmaxf(acc2[n4 * 4 + 1], 0.f);
        v.z = fmaxf(acc2[n4 * 4 + 2], 0.f);
        v.w = fmaxf(acc2[n4 * 4 + 3], 0.f);
        *(float4*)&H2T[o * 36 + 4 * (n4 ^ operm)] = v;
    }
    __syncthreads();

    // ---- cs2 ----
    {
        float s = 0.f;
#pragma unroll
        for (int g = 0; g < 8; g++) {
            float4 v = *(const float4*)&H2T[tid * 36 + 4 * g];
            s += v.x + v.y + v.z + v.w;
        }
        CS[tid] = s;
    }
    __syncthreads();

    // ---- stage full W2_2T [256 d][129] ----
    for (int i = tid; i < 32768; i += 256) {
        int d = i >> 7, oo = i & 127;
        W[d * 129 + oo] = g_w22t[d * 128 + oo];
    }
    __syncthreads();

    // ---- sage2 (threads o<128): v2 + GEMM over 256 d, write out ----
    if (o < 128) {
        float v = 0.f;
        for (int d = 0; d < 256; d += 4) {
            v += CS[d] * g_l2t[d * 128 + o] + CS[d + 1] * g_l2t[(d + 1) * 128 + o] +
                 CS[d + 2] * g_l2t[(d + 2) * 128 + o] +
                 CS[d + 3] * g_l2t[(d + 3) * 128 + o];
        }
        float acc3[32];
        float init = v * C + s2lb[o];
#pragma unroll
        for (int n = 0; n < 32; n++) acc3[n] = init;
        for (int d = 0; d < 256; d++) {
            float w = W[d * 129 + o];
            int dperm = d & 7;
#pragma unroll
            for (int n4 = 0; n4 < 8; n4++) {
                float4 hv = *(const float4*)&H2T[d * 36 + 4 * (n4 ^ dperm)];
                acc3[n4 * 4 + 0] += hv.x * w;
                acc3[n4 * 4 + 1] += hv.y * w;
                acc3[n4 * 4 + 2] += hv.z * w;
                acc3[n4 * 4 + 3] += hv.w * w;
            }
        }
#pragma unroll
        for (int n = 0; n < 32; n++)
            out[(b * 32 + n) * 128 + o] = acc3[n];
    }
}

// ---------------------------------------------------------------------------
extern "C" void kernel_launch(void* const* d_in, const int* in_sizes, int n_in,
                              void* d_out, int out_size) {
    const float* x    = (const float*)d_in[0];
    const float* mask = (const float*)d_in[1];
    const float* c1w  = (const float*)d_in[2];
    const float* c1b  = (const float*)d_in[3];
    const float* c2w  = (const float*)d_in[4];
    const float* c2b  = (const float*)d_in[5];
    const float* fcw  = (const float*)d_in[6];
    const float* fcb  = (const float*)d_in[7];
    const float* s1lw = (const float*)d_in[8];
    const float* s1lb = (const float*)d_in[9];
    const float* s1rw = (const float*)d_in[10];
    const float* s2lw = (const float*)d_in[11];
    const float* s2lb = (const float*)d_in[12];
    const float* s2rw = (const float*)d_in[13];
    float* out = (float*)d_out;

    cudaFuncSetAttribute(conv2_mma, cudaFuncAttributeMaxDynamicSharedMemorySize,
                         C2_SMEM);
    cudaFuncSetAttribute(head_kernel, cudaFuncAttributeMaxDynamicSharedMemorySize,
                         HEAD_SMEM);

    prep_w<<<288, 256>>>(c2w);
    prep_sage<<<384, 256>>>(s1lw, s1rw, s2lw, s2rw);
    conv1_kernel<<<1024, 256>>>(x, c1w, c1b);
    conv2_mma<<<dim3(2, 1024), 256, C2_SMEM>>>(c2b);
    head_kernel<<<32, 256, HEAD_SMEM>>>(fcw, fcb, mask, s1lb, s2lb, out);
}

// round 9
// speedup vs baseline: 8.2175x; 1.0974x over previous
#include <cuda_runtime.h>
#include <cuda_fp16.h>
#include <cstdint>

// ===========================================================================
// GraphSageNet GB300 — round 8.
// conv2: single CTA per image (512 thr, 16 warps = 4px x 4oc), both oc-groups
//        resident -> slab staged ONCE per image, better latency hiding.
//        #pragma unroll on shift loop to constant-fold swizzled addresses.
// conv1: packed fma.rn.f32x2.  head: fused fc+sage1+sage2 (folded weights).
// ===========================================================================

#define NPAD 1280
#define GUARD 64
#define ROWS_TOTAL (GUARD + 1024 * NPAD + GUARD)

__device__ __align__(16) __half g_act[(size_t)ROWS_TOTAL * 64];
__device__ __align__(16) __half g_wh[2 * 9 * 4096];
__device__ __align__(16) float g_pp[1024 * 128];
__device__ __align__(16) float g_w21t[256 * 256];
__device__ __align__(16) float g_l1t [256 * 256];
__device__ __align__(16) float g_w22t[256 * 128];
__device__ __align__(16) float g_l2t [256 * 128];

// ------------------------------- helpers -----------------------------------
__device__ __forceinline__ uint32_t smem_u32(const void* p) {
    uint32_t a;
    asm("{ .reg .u64 t; cvta.to.shared.u64 t, %1; cvt.u32.u64 %0, t; }"
        : "=r"(a) : "l"(p));
    return a;
}
__device__ __forceinline__ void ldsm4(uint32_t r[4], uint32_t addr) {
    asm volatile("ldmatrix.sync.aligned.m8n8.x4.shared.b16 {%0,%1,%2,%3}, [%4];"
                 : "=r"(r[0]), "=r"(r[1]), "=r"(r[2]), "=r"(r[3]) : "r"(addr));
}
__device__ __forceinline__ void mma16816(float* d, const uint32_t a[4],
                                         uint32_t b0, uint32_t b1) {
    asm volatile(
        "mma.sync.aligned.m16n8k16.row.col.f32.f16.f16.f32 "
        "{%0,%1,%2,%3}, {%4,%5,%6,%7}, {%8,%9}, {%0,%1,%2,%3};"
        : "+f"(d[0]), "+f"(d[1]), "+f"(d[2]), "+f"(d[3])
        : "r"(a[0]), "r"(a[1]), "r"(a[2]), "r"(a[3]), "r"(b0), "r"(b1));
}
#define CPA16(dst, src) \
    asm volatile("cp.async.cg.shared.global [%0], [%1], 16;" \
                 :: "r"(dst), "l"(src) : "memory")
#define CPA_COMMIT() asm volatile("cp.async.commit_group;" ::: "memory")

__device__ __forceinline__ unsigned long long pack2(float lo, float hi) {
    unsigned long long d;
    asm("mov.b64 %0, {%1, %2};" : "=l"(d)
        : "r"(__float_as_uint(lo)), "r"(__float_as_uint(hi)));
    return d;
}
__device__ __forceinline__ void unpack2(unsigned long long v, float& lo, float& hi) {
    unsigned a, b;
    asm("mov.b64 {%0, %1}, %2;" : "=r"(a), "=r"(b) : "l"(v));
    lo = __uint_as_float(a); hi = __uint_as_float(b);
}
__device__ __forceinline__ void fma2(unsigned long long& d, unsigned long long a,
                                     unsigned long long b, unsigned long long c) {
    asm("fma.rn.f32x2 %0, %1, %2, %3;" : "=l"(d) : "l"(a), "l"(b), "l"(c));
}

// ---------------------------------------------------------------------------
// prep_w: conv2 weights -> fp16, SW128-swizzled [ocg 2][s 9][64 x 128B]
// ---------------------------------------------------------------------------
__global__ void prep_w(const float* __restrict__ w) {
    int idx = blockIdx.x * 256 + threadIdx.x;
    if (idx >= 128 * 64 * 9) return;
    int s = idx % 9, t = idx / 9;
    int ic = t % 64, oc = t / 64;
    float v = w[oc * 576 + ic * 9 + s];
    int ocg = oc >> 6, ocl = oc & 63;
    uint32_t off = (uint32_t)(ocl * 128 + ic * 2);
    uint32_t sw = off ^ ((off >> 3) & 0x70);
    uint32_t base = ((uint32_t)ocg * 9 + (uint32_t)s) * 8192u;
    *(__half*)((char*)g_wh + base + sw) = __float2half_rn(v);
}

// ---------------------------------------------------------------------------
// prep_sage: W2 = rw - lw/31 (transposed [d][o]) + lw transposed
// ---------------------------------------------------------------------------
__global__ void prep_sage(const float* __restrict__ s1lw,
                          const float* __restrict__ s1rw,
                          const float* __restrict__ s2lw,
                          const float* __restrict__ s2rw) {
    const float C = 1.f / 31.f;
    int idx = blockIdx.x * 256 + threadIdx.x;
    if (idx < 65536) {
        int o = idx >> 8, d = idx & 255;
        float l = s1lw[idx];
        g_w21t[d * 256 + o] = s1rw[idx] - C * l;
        g_l1t [d * 256 + o] = l;
    } else if (idx < 98304) {
        int j = idx - 65536;
        int o = j >> 8, d = j & 255;
        float l = s2lw[j];
        g_w22t[d * 128 + o] = s2rw[j] - C * l;
        g_l2t [d * 128 + o] = l;
    }
}

// ---------------------------------------------------------------------------
// conv1: [1024,3,32,32] -> relu -> fp16 padded px-major; packed f32x2 FMA
// ---------------------------------------------------------------------------
__global__ void __launch_bounds__(256) conv1_kernel(const float* __restrict__ x,
                                                    const float* __restrict__ w,
                                                    const float* __restrict__ b) {
    __shared__ __align__(16) float ws[27 * 64];
    __shared__ __align__(16) float xs[3 * 34 * 35];

    const int n = blockIdx.x, tid = threadIdx.x;

    for (int i = tid; i < 3 * 34 * 35; i += 256) xs[i] = 0.f;
    for (int i = tid; i < 64 * 27; i += 256) {
        int oc = i / 27, k = i % 27;
        ws[k * 64 + oc] = w[i];
    }
    __syncthreads();
    const float* xin = x + n * 3072;
    for (int i = tid; i < 3072; i += 256) {
        int ic = i >> 10, r = (i >> 5) & 31, c = i & 31;
        xs[ic * (34 * 35) + (r + 1) * 35 + (c + 1)] = xin[i];
    }
    __syncthreads();

    const int ocq = tid >> 5, oc0 = ocq * 8;
    unsigned long long bp[8];
#pragma unroll
    for (int j = 0; j < 8; j++) {
        float bv = b[oc0 + j];
        bp[j] = pack2(bv, bv);
    }

    for (int it = 0; it < 4; it++) {
        int pg = it * 32 + (tid & 31);
        int row = pg >> 2, colb = (pg & 3) * 8;
        unsigned long long acc[8][4];
#pragma unroll
        for (int j = 0; j < 8; j++)
#pragma unroll
            for (int t = 0; t < 4; t++) acc[j][t] = bp[j];

#pragma unroll
        for (int ic = 0; ic < 3; ic++)
#pragma unroll
            for (int kr = 0; kr < 3; kr++) {
                int base = ic * (34 * 35) + (row + kr) * 35 + colb;
                float in10[10];
#pragma unroll
                for (int q = 0; q < 10; q++) in10[q] = xs[base + q];
#pragma unroll
                for (int kc = 0; kc < 3; kc++) {
                    int k = ic * 9 + kr * 3 + kc;
                    float4 w0 = *(const float4*)&ws[k * 64 + oc0];
                    float4 w1 = *(const float4*)&ws[k * 64 + oc0 + 4];
                    float wv[8] = {w0.x, w0.y, w0.z, w0.w, w1.x, w1.y, w1.z, w1.w};
                    unsigned long long ip[4];
#pragma unroll
                    for (int t = 0; t < 4; t++)
                        ip[t] = pack2(in10[kc + 2 * t], in10[kc + 2 * t + 1]);
#pragma unroll
                    for (int j = 0; j < 8; j++) {
                        unsigned long long wp = pack2(wv[j], wv[j]);
#pragma unroll
                        for (int t = 0; t < 4; t++) fma2(acc[j][t], wp, ip[t], acc[j][t]);
                    }
                }
            }
#pragma unroll
        for (int p = 0; p < 8; p++) {
            int col = colb + p;
            size_t pxa = (size_t)GUARD + (size_t)n * NPAD + (row + 1) * 34 + (col + 1);
            uint32_t q[4];
#pragma unroll
            for (int pr = 0; pr < 4; pr++) {
                float a0l, a0h, a1l, a1h;
                unpack2(acc[2 * pr][p >> 1], a0l, a0h);
                unpack2(acc[2 * pr + 1][p >> 1], a1l, a1h);
                float v0 = (p & 1) ? a0h : a0l;
                float v1 = (p & 1) ? a1h : a1l;
                __half h0 = __float2half_rn(fmaxf(v0, 0.f));
                __half h1 = __float2half_rn(fmaxf(v1, 0.f));
                q[pr] = (uint32_t)__half_as_ushort(h0) |
                        ((uint32_t)__half_as_ushort(h1) << 16);
            }
            *(uint4*)&g_act[pxa * 64 + oc0] = make_uint4(q[0], q[1], q[2], q[3]);
        }
    }
}

// ---------------------------------------------------------------------------
// conv2 via mma.sync: grid 1024 (one CTA per image), 512 threads (16 warps =
// 4 px-warps x 4 oc-warps, full 128 oc). Slab staged once per image.
// smem: Wh(2 ocg) 147456 | slab x2 50688 | bias 512 | red 2048  = 200704 B
// ---------------------------------------------------------------------------
#define SM_WH 0
#define SM_SLAB 147456
#define SLAB_BYTES 25344
#define SM_BIAS 198144
#define SM_RED 198656
#define C2_SMEM 200704

__global__ void __launch_bounds__(512, 1) conv2_mma(const float* __restrict__ bias) {
    extern __shared__ __align__(1024) char smc[];
    const uint32_t smb = smem_u32(smc);
    const int tid = threadIdx.x, wid = tid >> 5, lane = tid & 31;
    const int n = blockIdx.x;
    const int pxw = wid & 3, ocw = wid >> 2;   // ocw 0..3 -> oc = ocw*32..

    const size_t img_base = (size_t)GUARD + (size_t)n * NPAD;
    const uint4* ga = (const uint4*)g_act;

    // ---- stage ALL weights (both ocg) + slab 0 ----
    {
        const uint4* srcH = (const uint4*)g_wh;
        for (int i = tid; i < 9216; i += 512)
            CPA16(smb + SM_WH + i * 16, srcH + i);
        size_t gbase = (img_base - 35) * 8;
        for (int i = tid; i < 1584; i += 512) {
            int r = i >> 3, j = i & 7;
            uint32_t d = (uint32_t)(r * 128) +
                         (((uint32_t)(j * 16)) ^ ((uint32_t)((r & 7) << 4)));
            CPA16(smb + SM_SLAB + d, ga + gbase + (size_t)r * 8 + j);
        }
        CPA_COMMIT();
    }
    if (tid < 128) ((float*)(smc + SM_BIAS))[tid] = bias[tid];

    const int l15 = lane & 15;
    const uint32_t lk = (uint32_t)((lane >> 4) * 16);
    // B rows within this warp's ocg tile (ocg = ocw>>1, half = ocw&1)
    const uint32_t wgBase = (uint32_t)((ocw >> 1) * 9) * 8192u;
    const int rB0 = (ocw & 1) * 32 + l15, rB1 = rB0 + 16;
    const uint32_t swB0 = (uint32_t)((rB0 & 7) << 4);
    const uint32_t swB1 = (uint32_t)((rB1 & 7) << 4);

    float b8[8];
#pragma unroll
    for (int nt = 0; nt < 4; nt++)
#pragma unroll
        for (int bb = 0; bb < 2; bb++)
            b8[nt * 2 + bb] = bias[ocw * 32 + nt * 8 + (lane & 3) * 2 + bb];

    float psum[8];
#pragma unroll
    for (int i = 0; i < 8; i++) psum[i] = 0.f;

    asm volatile("cp.async.wait_group 0;" ::: "memory");
    __syncthreads();

    for (int t = 0; t < 9; t++) {
        if (t < 8) {
            size_t gbase = (img_base + (size_t)(t + 1) * 128 - 35) * 8;
            uint32_t sbase = smb + SM_SLAB + (uint32_t)(((t + 1) & 1) * SLAB_BYTES);
            for (int i = tid; i < 1584; i += 512) {
                int r = i >> 3, j = i & 7;
                uint32_t d = (uint32_t)(r * 128) +
                             (((uint32_t)(j * 16)) ^ ((uint32_t)((r & 7) << 4)));
                CPA16(sbase + d, ga + gbase + (size_t)r * 8 + j);
            }
            CPA_COMMIT();
            asm volatile("cp.async.wait_group 1;" ::: "memory");
        } else {
            asm volatile("cp.async.wait_group 0;" ::: "memory");
        }
        __syncthreads();

        const uint32_t sbA = smb + SM_SLAB + (uint32_t)((t & 1) * SLAB_BYTES);
        float acc[2][4][4];
#pragma unroll
        for (int mt = 0; mt < 2; mt++)
#pragma unroll
            for (int nt = 0; nt < 4; nt++)
#pragma unroll
                for (int rg = 0; rg < 4; rg++) acc[mt][nt][rg] = 0.f;

#pragma unroll
        for (int s = 0; s < 9; s++) {
            const int doff = (s / 3 - 1) * 34 + (s % 3 - 1);
            const int rA0 = 35 + doff + pxw * 32 + l15;
            const int rA1 = rA0 + 16;
            const uint32_t swA0 = (uint32_t)((rA0 & 7) << 4);
            const uint32_t swA1 = (uint32_t)((rA1 & 7) << 4);
            const uint32_t wt = wgBase + (uint32_t)(s * 8192);
#pragma unroll
            for (int k = 0; k < 4; k++) {
                const uint32_t kb = (uint32_t)(k * 32) + lk;
                uint32_t a0[4], a1[4], bh0[4], bh1[4];
                ldsm4(a0, sbA + (uint32_t)(rA0 * 128) + (kb ^ swA0));
                ldsm4(a1, sbA + (uint32_t)(rA1 * 128) + (kb ^ swA1));
                ldsm4(bh0, smb + SM_WH + wt + (uint32_t)(rB0 * 128) + (kb ^ swB0));
                ldsm4(bh1, smb + SM_WH + wt + (uint32_t)(rB1 * 128) + (kb ^ swB1));
                mma16816(acc[0][0], a0, bh0[0], bh0[2]);
                mma16816(acc[0][1], a0, bh0[1], bh0[3]);
                mma16816(acc[0][2], a0, bh1[0], bh1[2]);
                mma16816(acc[0][3], a0, bh1[1], bh1[3]);
                mma16816(acc[1][0], a1, bh0[0], bh0[2]);
                mma16816(acc[1][1], a1, bh0[1], bh0[3]);
                mma16816(acc[1][2], a1, bh1[0], bh1[2]);
                mma16816(acc[1][3], a1, bh1[1], bh1[3]);
            }
        }

        bool inter[2][2];
#pragma unroll
        for (int mt = 0; mt < 2; mt++)
#pragma unroll
            for (int hh = 0; hh < 2; hh++) {
                int pl = t * 128 + pxw * 32 + mt * 16 + (lane >> 2) + hh * 8;
                int rr = pl / 34, cc = pl - rr * 34;
                inter[mt][hh] =
                    (pl < 1156) & (rr >= 1) & (rr <= 32) & (cc >= 1) & (cc <= 32);
            }
#pragma unroll
        for (int mt = 0; mt < 2; mt++)
#pragma unroll
            for (int nt = 0; nt < 4; nt++)
#pragma unroll
                for (int rg = 0; rg < 4; rg++) {
                    float v = fmaxf(acc[mt][nt][rg] + b8[nt * 2 + (rg & 1)], 0.f);
                    if (inter[mt][rg >> 1]) psum[nt * 2 + (rg & 1)] += v;
                }
        __syncthreads();
    }

#pragma unroll
    for (int off = 4; off <= 16; off <<= 1)
#pragma unroll
        for (int i = 0; i < 8; i++)
            psum[i] += __shfl_xor_sync(0xffffffffu, psum[i], off);

    float* red = (float*)(smc + SM_RED);   // [16 warps][32 cols]
    if (lane < 4) {
#pragma unroll
        for (int nt = 0; nt < 4; nt++)
#pragma unroll
            for (int bb = 0; bb < 2; bb++)
                red[wid * 32 + nt * 8 + lane * 2 + bb] = psum[nt * 2 + bb];
    }
    __syncthreads();
    if (tid < 128) {
        int og = tid >> 5, c = tid & 31;
        float s = 0.f;
#pragma unroll
        for (int p = 0; p < 4; p++) s += red[(og * 4 + p) * 32 + c];
        g_pp[n * 128 + og * 32 + c] = s;
    }
}

// ---------------------------------------------------------------------------
// head: fc + mask + sage1(relu) + sage2, one block per batch b (grid 32).
// ---------------------------------------------------------------------------
#define HS_PS 0
#define HS_W 16384
#define HS_HT 148480
#define HS_H2T 185344
#define HS_CS 222208
#define HS_MK 223232
#define HEAD_SMEM 223360

__global__ void __launch_bounds__(256, 1) head_kernel(
    const float* __restrict__ fcw, const float* __restrict__ fcb,
    const float* __restrict__ mask,
    const float* __restrict__ s1lb, const float* __restrict__ s2lb,
    float* __restrict__ out) {
    extern __shared__ __align__(16) float sh[];
    float* PS  = sh + HS_PS / 4;
    float* W   = sh + HS_W / 4;
    float* HT  = sh + HS_HT / 4;
    float* H2T = sh + HS_H2T / 4;
    float* CS  = sh + HS_CS / 4;
    float* MK  = sh + HS_MK / 4;

    const int b = blockIdx.x, tid = threadIdx.x;
    const float C = 1.f / 31.f;

    for (int i = tid; i < 32 * 128; i += 256)
        PS[i] = g_pp[b * 32 * 128 + i] * (1.f / 1024.f);
    for (int i = tid; i < 32768; i += 256) {
        int o = i >> 7, d = i & 127;
        W[d * 257 + o] = fcw[i];
    }
    if (tid < 32) MK[tid] = mask[b * 32 + tid];
    __syncthreads();

    const int o = tid;
    const int operm = o & 7;

    // ---- fc ----
    {
        float acc[32];
#pragma unroll
        for (int n = 0; n < 32; n++) acc[n] = 0.f;
        const float4* ps4 = (const float4*)PS;
        for (int d4 = 0; d4 < 32; d4++) {
            float w0 = W[(4 * d4 + 0) * 257 + o];
            float w1 = W[(4 * d4 + 1) * 257 + o];
            float w2 = W[(4 * d4 + 2) * 257 + o];
            float w3 = W[(4 * d4 + 3) * 257 + o];
#pragma unroll
            for (int n = 0; n < 32; n++) {
                float4 p = ps4[n * 32 + d4];
                acc[n] += p.x * w0 + p.y * w1 + p.z * w2 + p.w * w3;
            }
        }
        float bb = fcb[o];
#pragma unroll
        for (int n4 = 0; n4 < 8; n4++) {
            float4 v;
            v.x = (acc[n4 * 4 + 0] + bb) * MK[n4 * 4 + 0];
            v.y = (acc[n4 * 4 + 1] + bb) * MK[n4 * 4 + 1];
            v.z = (acc[n4 * 4 + 2] + bb) * MK[n4 * 4 + 2];
            v.w = (acc[n4 * 4 + 3] + bb) * MK[n4 * 4 + 3];
            *(float4*)&HT[o * 36 + 4 * (n4 ^ operm)] = v;
        }
    }
    __syncthreads();

    // ---- cs ----
    {
        float s = 0.f;
#pragma unroll
        for (int g = 0; g < 8; g++) {
            float4 v = *(const float4*)&HT[tid * 36 + 4 * g];
            s += v.x + v.y + v.z + v.w;
        }
        CS[tid] = s;
    }
    __syncthreads();

    // ---- v1 + sage1 ----
    float acc2[32];
    {
        float v = 0.f;
        for (int d = 0; d < 256; d += 4) {
            v += CS[d] * g_l1t[d * 256 + o] + CS[d + 1] * g_l1t[(d + 1) * 256 + o] +
                 CS[d + 2] * g_l1t[(d + 2) * 256 + o] +
                 CS[d + 3] * g_l1t[(d + 3) * 256 + o];
        }
        float init = v * C + s1lb[o];
#pragma unroll
        for (int n = 0; n < 32; n++) acc2[n] = init;
    }
    for (int c = 0; c < 2; c++) {
        __syncthreads();
        for (int i = tid; i < 32768; i += 256) {
            int dd = i >> 8, oo = i & 255;
            W[dd * 257 + oo] = g_w21t[(c * 128 + dd) * 256 + oo];
        }
        __syncthreads();
        for (int dd = 0; dd < 128; dd++) {
            int d = c * 128 + dd;
            float w = W[dd * 257 + o];
            int dperm = d & 7;
#pragma unroll
            for (int n4 = 0; n4 < 8; n4++) {
                float4 hv = *(const float4*)&HT[d * 36 + 4 * (n4 ^ dperm)];
                acc2[n4 * 4 + 0] += hv.x * w;
                acc2[n4 * 4 + 1] += hv.y * w;
                acc2[n4 * 4 + 2] += hv.z * w;
                acc2[n4 * 4 + 3] += hv.w * w;
            }
        }
    }
#pragma unroll
    for (int n4 = 0; n4 < 8; n4++) {
        float4 v;
        v.x = fmaxf(acc2[n4 * 4 + 0], 0.f);
        v.y = fmaxf(acc2[n4 * 4 + 1], 0.f);
        v.z = fmaxf(acc2[n4 * 4 + 2], 0.f);
        v.w = fmaxf(acc2[n4 * 4 + 3], 0.f);
        *(float4*)&H2T[o * 36 + 4 * (n4 ^ operm)] = v;
    }
    __syncthreads();

    // ---- cs2 ----
    {
        float s = 0.f;
#pragma unroll
        for (int g = 0; g < 8; g++) {
            float4 v = *(const float4*)&H2T[tid * 36 + 4 * g];
            s += v.x + v.y + v.z + v.w;
        }
        CS[tid] = s;
    }
    __syncthreads();

    for (int i = tid; i < 32768; i += 256) {
        int d = i >> 7, oo = i & 127;
        W[d * 129 + oo] = g_w22t[d * 128 + oo];
    }
    __syncthreads();

    if (o < 128) {
        float v = 0.f;
        for (int d = 0; d < 256; d += 4) {
            v += CS[d] * g_l2t[d * 128 + o] + CS[d + 1] * g_l2t[(d + 1) * 128 + o] +
                 CS[d + 2] * g_l2t[(d + 2) * 128 + o] +
                 CS[d + 3] * g_l2t[(d + 3) * 128 + o];
        }
        float acc3[32];
        float init = v * C + s2lb[o];
#pragma unroll
        for (int n = 0; n < 32; n++) acc3[n] = init;
        for (int d = 0; d < 256; d++) {
            float w = W[d * 129 + o];
            int dperm = d & 7;
#pragma unroll
            for (int n4 = 0; n4 < 8; n4++) {
                float4 hv = *(const float4*)&H2T[d * 36 + 4 * (n4 ^ dperm)];
                acc3[n4 * 4 + 0] += hv.x * w;
                acc3[n4 * 4 + 1] += hv.y * w;
                acc3[n4 * 4 + 2] += hv.z * w;
                acc3[n4 * 4 + 3] += hv.w * w;
            }
        }
#pragma unroll
        for (int n = 0; n < 32; n++)
            out[(b * 32 + n) * 128 + o] = acc3[n];
    }
}

// ---------------------------------------------------------------------------
extern "C" void kernel_launch(void* const* d_in, const int* in_sizes, int n_in,
                              void* d_out, int out_size) {
    const float* x    = (const float*)d_in[0];
    const float* mask = (const float*)d_in[1];
    const float* c1w  = (const float*)d_in[2];
    const float* c1b  = (const float*)d_in[3];
    const float* c2w  = (const float*)d_in[4];
    const float* c2b  = (const float*)d_in[5];
    const float* fcw  = (const float*)d_in[6];
    const float* fcb  = (const float*)d_in[7];
    const float* s1lw = (const float*)d_in[8];
    const float* s1lb = (const float*)d_in[9];
    const float* s1rw = (const float*)d_in[10];
    const float* s2lw = (const float*)d_in[11];
    const float* s2lb = (const float*)d_in[12];
    const float* s2rw = (const float*)d_in[13];
    float* out = (float*)d_out;

    cudaFuncSetAttribute(conv2_mma, cudaFuncAttributeMaxDynamicSharedMemorySize,
                         C2_SMEM);
    cudaFuncSetAttribute(head_kernel, cudaFuncAttributeMaxDynamicSharedMemorySize,
                         HEAD_SMEM);

    prep_w<<<288, 256>>>(c2w);
    prep_sage<<<384, 256>>>(s1lw, s1rw, s2lw, s2rw);
    conv1_kernel<<<1024, 256>>>(x, c1w, c1b);
    conv2_mma<<<1024, 512, C2_SMEM>>>(c2b);
    head_kernel<<<32, 256, HEAD_SMEM>>>(fcw, fcb, mask, s1lb, s2lb, out);
}